// round 1
// baseline (speedup 1.0000x reference)
#include <cuda_runtime.h>
#include <cstdint>

// ---------------- problem capacities (compile-time) ----------------
#define NODES_MAX 50000
#define EDGE_MAX  860000
#define KD 256          // inner K dim for all GEMMs (D_IN and H*D_HID)

// ---------------- device scratch (no allocation allowed) -----------
__device__ float g_fs1[NODES_MAX * 256];
__device__ float g_h1 [NODES_MAX * 256];
__device__ float g_fs2[NODES_MAX * 128];
__device__ float g_res2[NODES_MAX * 128];
__device__ float g_el [NODES_MAX * 4];
__device__ float g_er [NODES_MAX * 4];
__device__ int   g_emax[NODES_MAX * 4];
__device__ float g_denom[NODES_MAX * 4];
__device__ float g_ex [EDGE_MAX * 4];     // attention numerators, CSR-ordered
__device__ int   g_cnt[NODES_MAX];
__device__ int   g_cursor[NODES_MAX];
__device__ int   g_rowptr[NODES_MAX + 1];
__device__ int   g_csr_src[EDGE_MAX];
__device__ int   g_epos[EDGE_MAX];        // edge -> CSR slot
__device__ float g_ur1[256 * 4];
__device__ float g_ur2[256 * 4];

// ---------------- helpers ----------------
__device__ __forceinline__ int enc_f(float f) {
    int i = __float_as_int(f);
    return i >= 0 ? i : (i ^ 0x7FFFFFFF);
}
__device__ __forceinline__ float dec_f(int i) {
    return __int_as_float(i >= 0 ? i : (i ^ 0x7FFFFFFF));
}
__device__ __forceinline__ float lrelu(float x) { return x < 0.f ? 0.2f * x : x; }

__device__ __forceinline__ void fma2(unsigned long long& acc, unsigned long long a,
                                     unsigned long long b) {
    asm("fma.rn.f32x2 %0, %1, %2, %0;" : "+l"(acc) : "l"(a), "l"(b));
}
__device__ __forceinline__ unsigned long long pack2(float x) {
    unsigned long long r;
    unsigned u = __float_as_uint(x);
    asm("mov.b64 %0, {%1, %1};" : "=l"(r) : "r"(u));
    return r;
}
__device__ __forceinline__ void unpack2(unsigned long long v, float& lo, float& hi) {
    unsigned a, b;
    asm("mov.b64 {%0, %1}, %2;" : "=r"(a), "=r"(b) : "l"(v));
    lo = __uint_as_float(a);
    hi = __uint_as_float(b);
}

// ---------------- small setup kernels ----------------
__global__ void k_clear_graph(int* cnt, int* cursor, int n) {
    int i = blockIdx.x * blockDim.x + threadIdx.x;
    if (i < n) { cnt[i] = 0; cursor[i] = 0; }
}
__global__ void k_clear_seg(int* emax, float* denom, int n4) {
    int i = blockIdx.x * blockDim.x + threadIdx.x;
    if (i < n4) { emax[i] = INT_MIN; denom[i] = 0.f; }
}
__global__ void k_count(const int* __restrict__ dst, int* cnt, int e_cnt) {
    int e = blockIdx.x * blockDim.x + threadIdx.x;
    if (e < e_cnt) atomicAdd(&cnt[dst[e]], 1);
}
__global__ void k_scan(const int* __restrict__ cnt, int* rowptr, int n) {
    __shared__ int sh[1024];
    __shared__ int s_run;
    int t = threadIdx.x;
    if (t == 0) s_run = 0;
    __syncthreads();
    for (int base = 0; base < n; base += 1024) {
        int idx = base + t;
        int x = (idx < n) ? cnt[idx] : 0;
        sh[t] = x;
        __syncthreads();
        #pragma unroll
        for (int off = 1; off < 1024; off <<= 1) {
            int v = (t >= off) ? sh[t - off] : 0;
            __syncthreads();
            sh[t] += v;
            __syncthreads();
        }
        int incl = sh[t];
        if (idx < n) rowptr[idx] = s_run + incl - x;
        int tot = sh[1023];
        __syncthreads();
        if (t == 0) s_run += tot;
        __syncthreads();
    }
    if (t == 0) rowptr[n] = s_run;
}
__global__ void k_fill(const int* __restrict__ src, const int* __restrict__ dst,
                       const int* __restrict__ rowptr, int* cursor,
                       int* csr_src, int* epos, int e_cnt) {
    int e = blockIdx.x * blockDim.x + threadIdx.x;
    if (e >= e_cnt) return;
    int d = dst[e];
    int p = rowptr[d] + atomicAdd(&cursor[d], 1);
    csr_src[p] = src[e];
    epos[e] = p;
}
// ur[k,h] = sum_d W_dst[k, h*D+d] * ar[h,d]  (folds fd-projection into a [256,4] GEMM)
__global__ void k_ur(const float* __restrict__ W1d, const float* __restrict__ ar1,
                     const float* __restrict__ W2d, const float* __restrict__ ar2,
                     float* ur1, float* ur2) {
    int k = threadIdx.x;  // 0..255
    if (blockIdx.x == 0) {
        for (int h = 0; h < 4; h++) {
            float s = 0.f;
            for (int d = 0; d < 64; d++) s += W1d[k * 256 + h * 64 + d] * ar1[h * 64 + d];
            ur1[k * 4 + h] = s;
        }
    } else {
        for (int h = 0; h < 4; h++) {
            float s = 0.f;
            for (int d = 0; d < 32; d++) s += W2d[k * 128 + h * 32 + d] * ar2[h * 32 + d];
            ur2[k * 4 + h] = s;
        }
    }
}

// ---------------- GEMM: C[M,Nc] = A[M,256] * B[256,Nc] (fp32, f32x2 packed) -----
// block 256 threads, BM=128, BN=64, BK=16; thread tile 8x4 (rows paired for f32x2)
__global__ __launch_bounds__(256) void k_gemm(const float* __restrict__ A,
                                              const float* __restrict__ B,
                                              float* __restrict__ C, int M, int Nc) {
    __shared__ __align__(16) float As[16][130];  // transposed A tile (pad keeps 8B align)
    __shared__ __align__(16) float Bs[16][64];
    int t = threadIdx.x;
    int tx = t & 15;        // col group
    int ty = t >> 4;        // row group
    int bm = blockIdx.x * 128;
    int bn = blockIdx.y * 64;

    unsigned long long acc[4][4];  // [row-pair][col]
    #pragma unroll
    for (int i = 0; i < 4; i++)
        #pragma unroll
        for (int j = 0; j < 4; j++) acc[i][j] = 0ull;

    int ar = t >> 2;          // 0..63 (A load row within half-tile)
    int ac = (t & 3) * 4;     // 0,4,8,12
    int br = t >> 4;          // 0..15 (B load row)
    int bc = (t & 15) * 4;

    for (int k0 = 0; k0 < KD; k0 += 16) {
        #pragma unroll
        for (int rr = 0; rr < 2; rr++) {
            int row = bm + ar + rr * 64;
            float4 v = make_float4(0.f, 0.f, 0.f, 0.f);
            if (row < M) v = *(const float4*)&A[(size_t)row * KD + k0 + ac];
            As[ac + 0][ar + rr * 64] = v.x;
            As[ac + 1][ar + rr * 64] = v.y;
            As[ac + 2][ar + rr * 64] = v.z;
            As[ac + 3][ar + rr * 64] = v.w;
        }
        *(float4*)&Bs[br][bc] = *(const float4*)&B[(size_t)(k0 + br) * Nc + bn + bc];
        __syncthreads();
        #pragma unroll
        for (int kk = 0; kk < 16; kk++) {
            unsigned long long a2[4];
            const double* ap = (const double*)&As[kk][ty * 8];
            #pragma unroll
            for (int rp = 0; rp < 4; rp++) a2[rp] = ((const unsigned long long*)ap)[rp];
            float4 bv = *(const float4*)&Bs[kk][tx * 4];
            unsigned long long b2[4] = {pack2(bv.x), pack2(bv.y), pack2(bv.z), pack2(bv.w)};
            #pragma unroll
            for (int c = 0; c < 4; c++)
                #pragma unroll
                for (int rp = 0; rp < 4; rp++) fma2(acc[rp][c], a2[rp], b2[c]);
        }
        __syncthreads();
    }
    // store: rows bm + ty*8 + 2*rp (+1), cols bn + tx*4 .. +3
    #pragma unroll
    for (int rp = 0; rp < 4; rp++) {
        float lo[4], hi[4];
        #pragma unroll
        for (int c = 0; c < 4; c++) unpack2(acc[rp][c], lo[c], hi[c]);
        int r0 = bm + ty * 8 + rp * 2;
        int col = bn + tx * 4;
        if (r0 < M)     *(float4*)&C[(size_t)r0 * Nc + col]       = make_float4(lo[0], lo[1], lo[2], lo[3]);
        if (r0 + 1 < M) *(float4*)&C[(size_t)(r0 + 1) * Nc + col] = make_float4(hi[0], hi[1], hi[2], hi[3]);
    }
}

// ---------------- per-node attention scores: el (from fs), er (= A @ ur) ------
__global__ void k_scores(const float* __restrict__ fs, const float* __restrict__ Arow,
                         const float* __restrict__ ur, const float* __restrict__ al,
                         float* el, float* er, int D, int FS) {
    int n = blockIdx.x;
    int h = threadIdx.x >> 5;
    int lane = threadIdx.x & 31;
    float s = 0.f;
    for (int d = lane; d < D; d += 32) s += fs[(size_t)n * FS + h * D + d] * al[h * D + d];
    #pragma unroll
    for (int o = 16; o; o >>= 1) s += __shfl_xor_sync(0xFFFFFFFFu, s, o);
    float r = 0.f;
    for (int k = lane; k < 256; k += 32) r += Arow[(size_t)n * 256 + k] * ur[k * 4 + h];
    #pragma unroll
    for (int o = 16; o; o >>= 1) r += __shfl_xor_sync(0xFFFFFFFFu, r, o);
    if (lane == 0) { el[n * 4 + h] = s; er[n * 4 + h] = r; }
}

// ---------------- edge passes ----------------
__global__ void k_edge_max(const int* __restrict__ src, const int* __restrict__ dst,
                           const float* __restrict__ el, const float* __restrict__ er,
                           int* emax, int e_cnt) {
    int e = blockIdx.x * blockDim.x + threadIdx.x;
    if (e >= e_cnt) return;
    int s = src[e], d = dst[e];
    float4 a = *(const float4*)&el[s * 4];
    float4 b = *(const float4*)&er[d * 4];
    atomicMax(&emax[d * 4 + 0], enc_f(lrelu(a.x + b.x)));
    atomicMax(&emax[d * 4 + 1], enc_f(lrelu(a.y + b.y)));
    atomicMax(&emax[d * 4 + 2], enc_f(lrelu(a.z + b.z)));
    atomicMax(&emax[d * 4 + 3], enc_f(lrelu(a.w + b.w)));
}
__global__ void k_edge_exp(const int* __restrict__ src, const int* __restrict__ dst,
                           const float* __restrict__ el, const float* __restrict__ er,
                           const int* __restrict__ emax, const int* __restrict__ epos,
                           float* __restrict__ ex, float* denom, int e_cnt) {
    int e = blockIdx.x * blockDim.x + threadIdx.x;
    if (e >= e_cnt) return;
    int s = src[e], d = dst[e];
    float4 a = *(const float4*)&el[s * 4];
    float4 b = *(const float4*)&er[d * 4];
    float v0 = expf(lrelu(a.x + b.x) - dec_f(emax[d * 4 + 0]));
    float v1 = expf(lrelu(a.y + b.y) - dec_f(emax[d * 4 + 1]));
    float v2 = expf(lrelu(a.z + b.z) - dec_f(emax[d * 4 + 2]));
    float v3 = expf(lrelu(a.w + b.w) - dec_f(emax[d * 4 + 3]));
    int p = epos[e];
    *(float4*)&ex[(size_t)p * 4] = make_float4(v0, v1, v2, v3);
    atomicAdd(&denom[d * 4 + 0], v0);
    atomicAdd(&denom[d * 4 + 1], v1);
    atomicAdd(&denom[d * 4 + 2], v2);
    atomicAdd(&denom[d * 4 + 3], v3);
}

// ---------------- aggregation layer 1 (FS=256) + identity residual + ELU -----
__global__ void k_agg1(const int* __restrict__ rowptr, const int* __restrict__ csr_src,
                       const float* __restrict__ ex, const float* __restrict__ denom,
                       const float* __restrict__ fs, const float* __restrict__ hin,
                       float* __restrict__ h1) {
    int n = blockIdx.x;
    int tid = threadIdx.x;          // 256: (h,d) = (tid>>6, tid&63)
    int h = tid >> 6;
    int beg = rowptr[n], end = rowptr[n + 1];
    __shared__ int ss[64];
    float acc = 0.f;
    for (int base = beg; base < end; base += 64) {
        int m = min(64, end - base);
        __syncthreads();
        if (tid < m) ss[tid] = csr_src[base + tid];
        __syncthreads();
        #pragma unroll 4
        for (int i = 0; i < m; i++) {
            float w = ex[(size_t)(base + i) * 4 + h];
            acc += w * fs[(size_t)ss[i] * 256 + tid];
        }
    }
    float inv = 1.f / denom[n * 4 + h];
    float v = acc * inv + hin[(size_t)n * 256 + tid];
    v = v > 0.f ? v : expm1f(v);
    h1[(size_t)n * 256 + tid] = v;
}

// ---------------- aggregation layer 2 (FS=128) + proj residual + head-mean ---
__global__ void k_agg2(const int* __restrict__ rowptr, const int* __restrict__ csr_src,
                       const float* __restrict__ ex, const float* __restrict__ denom,
                       const float* __restrict__ fs, const float* __restrict__ res,
                       float* __restrict__ out) {
    int n = blockIdx.x;
    int tid = threadIdx.x;          // 128: (h,d) = (tid>>5, tid&31)
    int h = tid >> 5;
    int beg = rowptr[n], end = rowptr[n + 1];
    __shared__ int ss[64];
    __shared__ float sv[128];
    float acc = 0.f;
    for (int base = beg; base < end; base += 64) {
        int m = min(64, end - base);
        __syncthreads();
        if (tid < m) ss[tid] = csr_src[base + tid];
        __syncthreads();
        #pragma unroll 4
        for (int i = 0; i < m; i++) {
            float w = ex[(size_t)(base + i) * 4 + h];
            acc += w * fs[(size_t)ss[i] * 128 + tid];
        }
    }
    float inv = 1.f / denom[n * 4 + h];
    float v = acc * inv + res[(size_t)n * 128 + tid];
    sv[tid] = v;
    __syncthreads();
    if (tid < 32)
        out[(size_t)n * 32 + tid] =
            (sv[tid] + sv[32 + tid] + sv[64 + tid] + sv[96 + tid]) * 0.25f;
}

// ---------------- launch ----------------
extern "C" void kernel_launch(void* const* d_in, const int* in_sizes, int n_in,
                              void* d_out, int out_size) {
    const float* h      = (const float*)d_in[0];
    const int*   src    = (const int*)d_in[1];
    const int*   dst    = (const int*)d_in[2];
    const float* W1_src = (const float*)d_in[3];
    const float* W1_dst = (const float*)d_in[4];
    const float* al1    = (const float*)d_in[5];
    const float* ar1    = (const float*)d_in[6];
    const float* W2_src = (const float*)d_in[7];
    const float* W2_dst = (const float*)d_in[8];
    const float* al2    = (const float*)d_in[9];
    const float* ar2    = (const float*)d_in[10];
    const float* Wres2  = (const float*)d_in[11];
    float* out = (float*)d_out;

    int N = in_sizes[0] / 256;
    int E = in_sizes[1];

    float *fs1, *h1, *fs2, *res2, *el, *er, *denom, *ex, *ur1, *ur2;
    int *emax, *cnt, *cursor, *rowptr, *csr_src, *epos;
    cudaGetSymbolAddress((void**)&fs1, g_fs1);
    cudaGetSymbolAddress((void**)&h1, g_h1);
    cudaGetSymbolAddress((void**)&fs2, g_fs2);
    cudaGetSymbolAddress((void**)&res2, g_res2);
    cudaGetSymbolAddress((void**)&el, g_el);
    cudaGetSymbolAddress((void**)&er, g_er);
    cudaGetSymbolAddress((void**)&denom, g_denom);
    cudaGetSymbolAddress((void**)&ex, g_ex);
    cudaGetSymbolAddress((void**)&ur1, g_ur1);
    cudaGetSymbolAddress((void**)&ur2, g_ur2);
    cudaGetSymbolAddress((void**)&emax, g_emax);
    cudaGetSymbolAddress((void**)&cnt, g_cnt);
    cudaGetSymbolAddress((void**)&cursor, g_cursor);
    cudaGetSymbolAddress((void**)&rowptr, g_rowptr);
    cudaGetSymbolAddress((void**)&csr_src, g_csr_src);
    cudaGetSymbolAddress((void**)&epos, g_epos);

    int gE = (E + 255) / 256;
    int gN = (N + 255) / 256;
    int gN4 = (N * 4 + 255) / 256;
    int gemmM = (N + 127) / 128;

    // CSR build (shared by both layers)
    k_clear_graph<<<gN, 256>>>(cnt, cursor, N);
    k_count<<<gE, 256>>>(dst, cnt, E);
    k_scan<<<1, 1024>>>(cnt, rowptr, N);
    k_fill<<<gE, 256>>>(src, dst, rowptr, cursor, csr_src, epos, E);
    k_ur<<<2, 256>>>(W1_dst, ar1, W2_dst, ar2, ur1, ur2);

    // ---- layer 1 ----
    k_gemm<<<dim3(gemmM, 4), 256>>>(h, W1_src, fs1, N, 256);
    k_scores<<<N, 128>>>(fs1, h, ur1, al1, el, er, 64, 256);
    k_clear_seg<<<gN4, 256>>>(emax, denom, N * 4);
    k_edge_max<<<gE, 256>>>(src, dst, el, er, emax, E);
    k_edge_exp<<<gE, 256>>>(src, dst, el, er, emax, epos, ex, denom, E);
    k_agg1<<<N, 256>>>(rowptr, csr_src, ex, denom, fs1, h, h1);

    // ---- layer 2 ----
    k_gemm<<<dim3(gemmM, 2), 256>>>(h1, W2_src, fs2, N, 128);
    k_gemm<<<dim3(gemmM, 2), 256>>>(h1, Wres2, res2, N, 128);
    k_scores<<<N, 128>>>(fs2, h1, ur2, al2, el, er, 32, 128);
    k_clear_seg<<<gN4, 256>>>(emax, denom, N * 4);
    k_edge_max<<<gE, 256>>>(src, dst, el, er, emax, E);
    k_edge_exp<<<gE, 256>>>(src, dst, el, er, emax, epos, ex, denom, E);
    k_agg2<<<N, 128>>>(rowptr, csr_src, ex, denom, fs2, res2, out);
}

// round 3
// speedup vs baseline: 1.3535x; 1.3535x over previous
#include <cuda_runtime.h>
#include <cuda_bf16.h>
#include <cstdint>

// ---------------- problem capacities ----------------
#define NODES_MAX 50000
#define EDGE_MAX  860000

// ---------------- device scratch ----------------
__device__ float g_fs1[NODES_MAX * 256];
__device__ float g_h1 [NODES_MAX * 256];
__device__ float g_fs2[NODES_MAX * 128];
__device__ float g_res2[NODES_MAX * 128];
__device__ float g_el [NODES_MAX * 4];
__device__ float g_er [NODES_MAX * 4];
__device__ float g_ex [EDGE_MAX * 4];          // normalized attention, CSR order
__device__ int   g_cnt[NODES_MAX];
__device__ int   g_cursor[NODES_MAX];
__device__ int   g_rowptr[NODES_MAX + 1];
__device__ int   g_partial[64];
__device__ int   g_csr_src[EDGE_MAX];
__device__ float g_ur1[256 * 4];
__device__ float g_ur2[256 * 4];
// bf16 split operands
__device__ __nv_bfloat16 g_Ahi[NODES_MAX * 256];
__device__ __nv_bfloat16 g_Alo[NODES_MAX * 256];
__device__ __nv_bfloat16 g_B1hi[256 * 256];   // W1_src transposed [n][k]
__device__ __nv_bfloat16 g_B1lo[256 * 256];
__device__ __nv_bfloat16 g_B2hi[128 * 256];
__device__ __nv_bfloat16 g_B2lo[128 * 256];
__device__ __nv_bfloat16 g_B3hi[128 * 256];
__device__ __nv_bfloat16 g_B3lo[128 * 256];

// ---------------- low-level helpers ----------------
__device__ __forceinline__ uint32_t smem_u32(const void* p) {
    uint32_t a;
    asm("{ .reg .u64 t; cvta.to.shared.u64 t, %1; cvt.u32.u64 %0, t; }" : "=r"(a) : "l"(p));
    return a;
}
__device__ __forceinline__ uint32_t swz(uint32_t o) { return o ^ ((o >> 3) & 0x70); }

__device__ __forceinline__ void cp16(uint32_t dst, const void* src, int sz) {
    asm volatile("cp.async.cg.shared.global [%0], [%1], 16, %2;"
                 :: "r"(dst), "l"(src), "r"(sz) : "memory");
}
__device__ __forceinline__ void cp_commit() {
    asm volatile("cp.async.commit_group;" ::: "memory");
}
template <int N>
__device__ __forceinline__ void cp_wait() {
    asm volatile("cp.async.wait_group %0;" :: "n"(N) : "memory");
}
__device__ __forceinline__ void ldm4(uint32_t* r, uint32_t addr) {
    asm volatile("ldmatrix.sync.aligned.m8n8.x4.shared.b16 {%0,%1,%2,%3}, [%4];"
                 : "=r"(r[0]), "=r"(r[1]), "=r"(r[2]), "=r"(r[3]) : "r"(addr));
}
__device__ __forceinline__ void mma_bf16(float* d, const uint32_t* a, const uint32_t* b) {
    asm volatile(
        "mma.sync.aligned.m16n8k16.row.col.f32.bf16.bf16.f32 "
        "{%0,%1,%2,%3}, {%4,%5,%6,%7}, {%8,%9}, {%0,%1,%2,%3};"
        : "+f"(d[0]), "+f"(d[1]), "+f"(d[2]), "+f"(d[3])
        : "r"(a[0]), "r"(a[1]), "r"(a[2]), "r"(a[3]), "r"(b[0]), "r"(b[1]));
}
__device__ __forceinline__ float lrelu(float x) { return x < 0.f ? 0.2f * x : x; }

// ---------------- setup kernels ----------------
__global__ void k_clear_graph(int* cnt, int* cursor, int n) {
    int i = blockIdx.x * blockDim.x + threadIdx.x;
    if (i < n) { cnt[i] = 0; cursor[i] = 0; }
}
__global__ void k_count(const int* __restrict__ dst, int* cnt, int e_cnt) {
    int e = blockIdx.x * blockDim.x + threadIdx.x;
    if (e < e_cnt) atomicAdd(&cnt[dst[e]], 1);
}
__global__ void k_scan1(const int* __restrict__ cnt, int* rowptr, int* partial, int n) {
    __shared__ int sh[1024];
    int t = threadIdx.x;
    int idx = blockIdx.x * 1024 + t;
    int x = (idx < n) ? cnt[idx] : 0;
    sh[t] = x;
    __syncthreads();
    #pragma unroll
    for (int off = 1; off < 1024; off <<= 1) {
        int v = (t >= off) ? sh[t - off] : 0;
        __syncthreads();
        sh[t] += v;
        __syncthreads();
    }
    if (idx < n) rowptr[idx] = sh[t] - x;
    if (t == 1023) partial[blockIdx.x] = sh[1023];
}
__global__ void k_scan2(int* partial, int nb) {
    if (threadIdx.x == 0) {
        int run = 0;
        for (int i = 0; i < nb; i++) { int v = partial[i]; partial[i] = run; run += v; }
    }
}
__global__ void k_scan3(int* rowptr, const int* __restrict__ partial, int n, int e_cnt) {
    int i = blockIdx.x * blockDim.x + threadIdx.x;
    if (i < n) rowptr[i] += partial[i >> 10];
    if (i == 0) rowptr[n] = e_cnt;
}
__global__ void k_fill(const int* __restrict__ src, const int* __restrict__ dst,
                       const int* __restrict__ rowptr, int* cursor, int* csr_src, int e_cnt) {
    int e = blockIdx.x * blockDim.x + threadIdx.x;
    if (e >= e_cnt) return;
    int d = dst[e];
    int p = rowptr[d] + atomicAdd(&cursor[d], 1);
    csr_src[p] = src[e];
}
__global__ void k_ur(const float* __restrict__ W1d, const float* __restrict__ ar1,
                     const float* __restrict__ W2d, const float* __restrict__ ar2,
                     float* ur1, float* ur2) {
    int k = threadIdx.x;
    if (blockIdx.x == 0) {
        for (int h = 0; h < 4; h++) {
            float s = 0.f;
            for (int d = 0; d < 64; d++) s += W1d[k * 256 + h * 64 + d] * ar1[h * 64 + d];
            ur1[k * 4 + h] = s;
        }
    } else {
        for (int h = 0; h < 4; h++) {
            float s = 0.f;
            for (int d = 0; d < 32; d++) s += W2d[k * 128 + h * 32 + d] * ar2[h * 32 + d];
            ur2[k * 4 + h] = s;
        }
    }
}

// ---------------- bf16 split conversions ----------------
__global__ void k_convA(const float* __restrict__ A, __nv_bfloat16* __restrict__ hi,
                        __nv_bfloat16* __restrict__ lo, int n4) {
    int i = blockIdx.x * blockDim.x + threadIdx.x;
    if (i >= n4) return;
    float4 v = *(const float4*)&A[(size_t)i * 4];
    __nv_bfloat16 h0 = __float2bfloat16(v.x), h1 = __float2bfloat16(v.y);
    __nv_bfloat16 h2 = __float2bfloat16(v.z), h3 = __float2bfloat16(v.w);
    __nv_bfloat16 l0 = __float2bfloat16(v.x - __bfloat162float(h0));
    __nv_bfloat16 l1 = __float2bfloat16(v.y - __bfloat162float(h1));
    __nv_bfloat16 l2 = __float2bfloat16(v.z - __bfloat162float(h2));
    __nv_bfloat16 l3 = __float2bfloat16(v.w - __bfloat162float(h3));
    __nv_bfloat162* hp = (__nv_bfloat162*)&hi[(size_t)i * 4];
    __nv_bfloat162* lp = (__nv_bfloat162*)&lo[(size_t)i * 4];
    hp[0] = __nv_bfloat162(h0, h1); hp[1] = __nv_bfloat162(h2, h3);
    lp[0] = __nv_bfloat162(l0, l1); lp[1] = __nv_bfloat162(l2, l3);
}
__global__ void k_convB(const float* __restrict__ W1, const float* __restrict__ W2,
                        const float* __restrict__ W3,
                        __nv_bfloat16* b1h, __nv_bfloat16* b1l,
                        __nv_bfloat16* b2h, __nv_bfloat16* b2l,
                        __nv_bfloat16* b3h, __nv_bfloat16* b3l) {
    int k = blockIdx.x;      // 0..255
    int n = threadIdx.x;
    const float* W; __nv_bfloat16 *bh, *bl; int Nc;
    if (blockIdx.y == 0)      { W = W1; bh = b1h; bl = b1l; Nc = 256; }
    else if (blockIdx.y == 1) { W = W2; bh = b2h; bl = b2l; Nc = 128; }
    else                      { W = W3; bh = b3h; bl = b3l; Nc = 128; }
    if (n >= Nc) return;
    float x = W[k * Nc + n];
    __nv_bfloat16 h = __float2bfloat16(x);
    bh[n * 256 + k] = h;
    bl[n * 256 + k] = __float2bfloat16(x - __bfloat162float(h));
}

// ---------------- HMMA GEMM: C[M,Nc] = A[M,256] * Bt[Nc,256]^T -----------------
// CTA tile 128x64, 8 warps (warp tile 32x32), BK=64, cp.async double-buffered.
// Split accumulation: AhBh + AlBh + AhBl (fp32 acc).
// Stage layout (49152 B): Ah@0 (16K), Al@16K, Bh@32K (8K), Bl@40K.
#define STG 49152
#define GEMM_SMEM (2 * STG)

__device__ __forceinline__ void g_loadA(uint32_t sb, const __nv_bfloat16* Ahi,
                                        const __nv_bfloat16* Alo, int bm, int kb,
                                        int M, int t) {
    #pragma unroll
    for (int i = 0; i < 4; i++) {
        int id = t + i * 256;
        int r = id >> 3, c = id & 7;
        int ga = bm + r;
        int sz = (ga < M) ? 16 : 0;
        if (ga >= M) ga = M - 1;
        size_t so = (size_t)ga * 256 + kb * 64 + c * 8;
        uint32_t o = swz((uint32_t)(r * 128 + c * 16));
        cp16(sb + o, Ahi + so, sz);
        cp16(sb + 16384 + o, Alo + so, sz);
    }
}
__device__ __forceinline__ void g_loadB(uint32_t sb, const __nv_bfloat16* Bhi,
                                        const __nv_bfloat16* Blo, int bn, int kb, int t) {
    #pragma unroll
    for (int i = 0; i < 2; i++) {
        int id = t + i * 256;
        int n = id >> 3, c = id & 7;
        size_t so = (size_t)(bn + n) * 256 + kb * 64 + c * 8;
        uint32_t o = swz((uint32_t)(n * 128 + c * 16));
        cp16(sb + 32768 + o, Bhi + so, 16);
        cp16(sb + 40960 + o, Blo + so, 16);
    }
}

__global__ __launch_bounds__(256, 2) void k_mma(
    const __nv_bfloat16* __restrict__ Ahi, const __nv_bfloat16* __restrict__ Alo,
    const __nv_bfloat16* __restrict__ Bhi, const __nv_bfloat16* __restrict__ Blo,
    float* __restrict__ C, int M, int Nc) {
    extern __shared__ char smem[];
    uint32_t sb = smem_u32(smem);
    int t = threadIdx.x;
    int lane = t & 31, wid = t >> 5;
    int wm = wid & 3, wn = wid >> 2;
    int bm = blockIdx.x * 128;
    int bn = blockIdx.y * 64;

    float acc[2][4][4];
    #pragma unroll
    for (int mt = 0; mt < 2; mt++)
        #pragma unroll
        for (int nt = 0; nt < 4; nt++)
            #pragma unroll
            for (int i = 0; i < 4; i++) acc[mt][nt][i] = 0.f;

    // precomputed fragment offsets (per-lane)
    int a_row = wm * 32 + (lane & 15);
    int a_ch  = lane >> 4;
    int b_row = wn * 32 + (lane & 7) + ((lane >> 4) & 1) * 8;
    int b_ch  = (lane >> 3) & 1;

    g_loadA(sb, Ahi, Alo, bm, 0, M, t);
    g_loadB(sb, Bhi, Blo, bn, 0, t);
    cp_commit();

    #pragma unroll
    for (int kb = 0; kb < 4; kb++) {
        uint32_t stage = sb + (kb & 1) * STG;
        if (kb < 3) {
            uint32_t nxt = sb + ((kb + 1) & 1) * STG;
            g_loadA(nxt, Ahi, Alo, bm, kb + 1, M, t);
            g_loadB(nxt, Bhi, Blo, bn, kb + 1, t);
            cp_commit();
            cp_wait<1>();
        } else {
            cp_wait<0>();
        }
        __syncthreads();

        #pragma unroll
        for (int ks = 0; ks < 4; ks++) {
            uint32_t ah[2][4], al[2][4], bh[4][2], bl[4][2];
            #pragma unroll
            for (int mt = 0; mt < 2; mt++) {
                uint32_t off = swz((uint32_t)((a_row + mt * 16) * 128 + (ks * 2 + a_ch) * 16));
                ldm4(ah[mt], stage + off);
                ldm4(al[mt], stage + 16384 + off);
            }
            #pragma unroll
            for (int p = 0; p < 2; p++) {
                uint32_t off = swz((uint32_t)((b_row + p * 16) * 128 + (ks * 2 + b_ch) * 16));
                uint32_t rh[4], rl[4];
                ldm4(rh, stage + 32768 + off);
                ldm4(rl, stage + 40960 + off);
                bh[p * 2][0] = rh[0]; bh[p * 2][1] = rh[1];
                bh[p * 2 + 1][0] = rh[2]; bh[p * 2 + 1][1] = rh[3];
                bl[p * 2][0] = rl[0]; bl[p * 2][1] = rl[1];
                bl[p * 2 + 1][0] = rl[2]; bl[p * 2 + 1][1] = rl[3];
            }
            #pragma unroll
            for (int mt = 0; mt < 2; mt++)
                #pragma unroll
                for (int nt = 0; nt < 4; nt++) {
                    mma_bf16(acc[mt][nt], ah[mt], bh[nt]);
                    mma_bf16(acc[mt][nt], al[mt], bh[nt]);
                    mma_bf16(acc[mt][nt], ah[mt], bl[nt]);
                }
        }
        __syncthreads();
    }

    // epilogue
    #pragma unroll
    for (int mt = 0; mt < 2; mt++) {
        int r0 = bm + wm * 32 + mt * 16 + (lane >> 2);
        #pragma unroll
        for (int nt = 0; nt < 4; nt++) {
            int c0 = bn + wn * 32 + nt * 8 + (lane & 3) * 2;
            if (r0 < M)
                *(float2*)&C[(size_t)r0 * Nc + c0] = make_float2(acc[mt][nt][0], acc[mt][nt][1]);
            if (r0 + 8 < M)
                *(float2*)&C[(size_t)(r0 + 8) * Nc + c0] = make_float2(acc[mt][nt][2], acc[mt][nt][3]);
        }
    }
}

// ---------------- per-node scores ----------------
__global__ void k_scores(const float* __restrict__ fs, const float* __restrict__ Arow,
                         const float* __restrict__ ur, const float* __restrict__ al,
                         float* el, float* er, int D, int FS) {
    int n = blockIdx.x;
    int h = threadIdx.x >> 5;
    int lane = threadIdx.x & 31;
    float s = 0.f;
    for (int d = lane; d < D; d += 32) s += fs[(size_t)n * FS + h * D + d] * al[h * D + d];
    #pragma unroll
    for (int o = 16; o; o >>= 1) s += __shfl_xor_sync(0xFFFFFFFFu, s, o);
    float r = 0.f;
    for (int k = lane; k < 256; k += 32) r += Arow[(size_t)n * 256 + k] * ur[k * 4 + h];
    #pragma unroll
    for (int o = 16; o; o >>= 1) r += __shfl_xor_sync(0xFFFFFFFFu, r, o);
    if (lane == 0) { el[n * 4 + h] = s; er[n * 4 + h] = r; }
}

// ---------------- fused CSR segment softmax: warp per node ----------------
__global__ void k_softmax(const int* __restrict__ rowptr, const int* __restrict__ csr_src,
                          const float* __restrict__ el, const float* __restrict__ er,
                          float* __restrict__ ex, int n_cnt) {
    int warp = (blockIdx.x * blockDim.x + threadIdx.x) >> 5;
    int lane = threadIdx.x & 31;
    if (warp >= n_cnt) return;
    int beg = rowptr[warp], end = rowptr[warp + 1];
    float4 erv = *(const float4*)&er[warp * 4];
    float m0 = -1e30f, m1 = -1e30f, m2 = -1e30f, m3 = -1e30f;
    for (int j = beg + lane; j < end; j += 32) {
        int s = csr_src[j];
        float4 e = *(const float4*)&el[s * 4];
        e.x = lrelu(e.x + erv.x); e.y = lrelu(e.y + erv.y);
        e.z = lrelu(e.z + erv.z); e.w = lrelu(e.w + erv.w);
        *(float4*)&ex[(size_t)j * 4] = e;
        m0 = fmaxf(m0, e.x); m1 = fmaxf(m1, e.y); m2 = fmaxf(m2, e.z); m3 = fmaxf(m3, e.w);
    }
    #pragma unroll
    for (int o = 16; o; o >>= 1) {
        m0 = fmaxf(m0, __shfl_xor_sync(0xFFFFFFFFu, m0, o));
        m1 = fmaxf(m1, __shfl_xor_sync(0xFFFFFFFFu, m1, o));
        m2 = fmaxf(m2, __shfl_xor_sync(0xFFFFFFFFu, m2, o));
        m3 = fmaxf(m3, __shfl_xor_sync(0xFFFFFFFFu, m3, o));
    }
    float s0 = 0.f, s1 = 0.f, s2 = 0.f, s3 = 0.f;
    for (int j = beg + lane; j < end; j += 32) {
        float4 e = *(const float4*)&ex[(size_t)j * 4];
        e.x = __expf(e.x - m0); e.y = __expf(e.y - m1);
        e.z = __expf(e.z - m2); e.w = __expf(e.w - m3);
        *(float4*)&ex[(size_t)j * 4] = e;
        s0 += e.x; s1 += e.y; s2 += e.z; s3 += e.w;
    }
    #pragma unroll
    for (int o = 16; o; o >>= 1) {
        s0 += __shfl_xor_sync(0xFFFFFFFFu, s0, o);
        s1 += __shfl_xor_sync(0xFFFFFFFFu, s1, o);
        s2 += __shfl_xor_sync(0xFFFFFFFFu, s2, o);
        s3 += __shfl_xor_sync(0xFFFFFFFFu, s3, o);
    }
    float i0 = 1.f / s0, i1 = 1.f / s1, i2 = 1.f / s2, i3 = 1.f / s3;
    for (int j = beg + lane; j < end; j += 32) {
        float4 e = *(const float4*)&ex[(size_t)j * 4];
        e.x *= i0; e.y *= i1; e.z *= i2; e.w *= i3;
        *(float4*)&ex[(size_t)j * 4] = e;
    }
}

// ---------------- aggregation ----------------
__global__ void k_agg1(const int* __restrict__ rowptr, const int* __restrict__ csr_src,
                       const float* __restrict__ ex, const float* __restrict__ fs,
                       const float* __restrict__ hin, float* __restrict__ h1) {
    int n = blockIdx.x;
    int tid = threadIdx.x;          // 256
    int h = tid >> 6;
    int beg = rowptr[n], end = rowptr[n + 1];
    __shared__ int ss[64];
    float acc = 0.f;
    for (int base = beg; base < end; base += 64) {
        int m = min(64, end - base);
        __syncthreads();
        if (tid < m) ss[tid] = csr_src[base + tid];
        __syncthreads();
        #pragma unroll 4
        for (int i = 0; i < m; i++) {
            float w = ex[(size_t)(base + i) * 4 + h];
            acc += w * fs[(size_t)ss[i] * 256 + tid];
        }
    }
    float v = acc + hin[(size_t)n * 256 + tid];
    v = v > 0.f ? v : expm1f(v);
    h1[(size_t)n * 256 + tid] = v;
}
__global__ void k_agg2(const int* __restrict__ rowptr, const int* __restrict__ csr_src,
                       const float* __restrict__ ex, const float* __restrict__ fs,
                       const float* __restrict__ res, float* __restrict__ out) {
    int n = blockIdx.x;
    int tid = threadIdx.x;          // 128
    int h = tid >> 5;
    int beg = rowptr[n], end = rowptr[n + 1];
    __shared__ int ss[64];
    __shared__ float sv[128];
    float acc = 0.f;
    for (int base = beg; base < end; base += 64) {
        int m = min(64, end - base);
        __syncthreads();
        if (tid < m) ss[tid] = csr_src[base + tid];
        __syncthreads();
        #pragma unroll 4
        for (int i = 0; i < m; i++) {
            float w = ex[(size_t)(base + i) * 4 + h];
            acc += w * fs[(size_t)ss[i] * 128 + tid];
        }
    }
    sv[tid] = acc + res[(size_t)n * 128 + tid];
    __syncthreads();
    if (tid < 32)
        out[(size_t)n * 32 + tid] =
            (sv[tid] + sv[32 + tid] + sv[64 + tid] + sv[96 + tid]) * 0.25f;
}

// ---------------- launch ----------------
extern "C" void kernel_launch(void* const* d_in, const int* in_sizes, int n_in,
                              void* d_out, int out_size) {
    const float* h      = (const float*)d_in[0];
    const int*   src    = (const int*)d_in[1];
    const int*   dst    = (const int*)d_in[2];
    const float* W1_src = (const float*)d_in[3];
    const float* W1_dst = (const float*)d_in[4];
    const float* al1    = (const float*)d_in[5];
    const float* ar1    = (const float*)d_in[6];
    const float* W2_src = (const float*)d_in[7];
    const float* W2_dst = (const float*)d_in[8];
    const float* al2    = (const float*)d_in[9];
    const float* ar2    = (const float*)d_in[10];
    const float* Wres2  = (const float*)d_in[11];
    float* out = (float*)d_out;

    int N = in_sizes[0] / 256;
    int E = in_sizes[1];

    float *fs1, *h1, *fs2, *res2, *el, *er, *ex, *ur1, *ur2;
    int *cnt, *cursor, *rowptr, *partial, *csr_src;
    __nv_bfloat16 *Ahi, *Alo, *B1h, *B1l, *B2h, *B2l, *B3h, *B3l;
    cudaGetSymbolAddress((void**)&fs1, g_fs1);
    cudaGetSymbolAddress((void**)&h1, g_h1);
    cudaGetSymbolAddress((void**)&fs2, g_fs2);
    cudaGetSymbolAddress((void**)&res2, g_res2);
    cudaGetSymbolAddress((void**)&el, g_el);
    cudaGetSymbolAddress((void**)&er, g_er);
    cudaGetSymbolAddress((void**)&ex, g_ex);
    cudaGetSymbolAddress((void**)&ur1, g_ur1);
    cudaGetSymbolAddress((void**)&ur2, g_ur2);
    cudaGetSymbolAddress((void**)&cnt, g_cnt);
    cudaGetSymbolAddress((void**)&cursor, g_cursor);
    cudaGetSymbolAddress((void**)&rowptr, g_rowptr);
    cudaGetSymbolAddress((void**)&partial, g_partial);
    cudaGetSymbolAddress((void**)&csr_src, g_csr_src);
    cudaGetSymbolAddress((void**)&Ahi, g_Ahi);
    cudaGetSymbolAddress((void**)&Alo, g_Alo);
    cudaGetSymbolAddress((void**)&B1h, g_B1hi);
    cudaGetSymbolAddress((void**)&B1l, g_B1lo);
    cudaGetSymbolAddress((void**)&B2h, g_B2hi);
    cudaGetSymbolAddress((void**)&B2l, g_B2lo);
    cudaGetSymbolAddress((void**)&B3h, g_B3hi);
    cudaGetSymbolAddress((void**)&B3l, g_B3lo);

    cudaFuncSetAttribute(k_mma, cudaFuncAttributeMaxDynamicSharedMemorySize, GEMM_SMEM);

    int gE = (E + 255) / 256;
    int gN = (N + 255) / 256;
    int nScanB = (N + 1023) / 1024;
    int gemmM = (N + 127) / 128;
    int gConvA = (N * 64 + 255) / 256;
    int gWarp = (N * 32 + 255) / 256;

    // CSR build + weight prep
    k_clear_graph<<<gN, 256>>>(cnt, cursor, N);
    k_count<<<gE, 256>>>(dst, cnt, E);
    k_scan1<<<nScanB, 1024>>>(cnt, rowptr, partial, N);
    k_scan2<<<1, 32>>>(partial, nScanB);
    k_scan3<<<gN, 256>>>(rowptr, partial, N, E);
    k_fill<<<gE, 256>>>(src, dst, rowptr, cursor, csr_src, E);
    k_ur<<<2, 256>>>(W1_dst, ar1, W2_dst, ar2, ur1, ur2);
    k_convB<<<dim3(256, 3), 256>>>(W1_src, W2_src, Wres2, B1h, B1l, B2h, B2l, B3h, B3l);

    // ---- layer 1 ----
    k_convA<<<gConvA, 256>>>(h, Ahi, Alo, N * 64);
    k_mma<<<dim3(gemmM, 4), 256, GEMM_SMEM>>>(Ahi, Alo, B1h, B1l, fs1, N, 256);
    k_scores<<<N, 128>>>(fs1, h, ur1, al1, el, er, 64, 256);
    k_softmax<<<gWarp, 256>>>(rowptr, csr_src, el, er, ex, N);
    k_agg1<<<N, 256>>>(rowptr, csr_src, ex, fs1, h, h1);

    // ---- layer 2 ----
    k_convA<<<gConvA, 256>>>(h1, Ahi, Alo, N * 64);
    k_mma<<<dim3(gemmM, 2), 256, GEMM_SMEM>>>(Ahi, Alo, B2h, B2l, fs2, N, 128);
    k_mma<<<dim3(gemmM, 2), 256, GEMM_SMEM>>>(Ahi, Alo, B3h, B3l, res2, N, 128);
    k_scores<<<N, 128>>>(fs2, h1, ur2, al2, el, er, 32, 128);
    k_softmax<<<gWarp, 256>>>(rowptr, csr_src, el, er, ex, N);
    k_agg2<<<N, 128>>>(rowptr, csr_src, ex, fs2, res2, out);
}

// round 4
// speedup vs baseline: 1.6517x; 1.2203x over previous
#include <cuda_runtime.h>
#include <cuda_bf16.h>
#include <cstdint>

// ---------------- problem capacities ----------------
#define NODES_MAX 50000
#define EDGE_MAX  860000

// ---------------- device scratch ----------------
__device__ float g_fs1[NODES_MAX * 256];
__device__ float g_c2 [NODES_MAX * 256];       // layer2 combined: cols 0-127 fs2, 128-255 res2
__device__ float g_el1[NODES_MAX * 4];
__device__ float g_el2[NODES_MAX * 4];
__device__ float g_er [NODES_MAX * 4];
__device__ float g_ex [EDGE_MAX * 4];
__device__ int   g_cnt[NODES_MAX];
__device__ int   g_cursor[NODES_MAX];
__device__ int   g_rowptr[NODES_MAX + 1];
__device__ int   g_partial[64];
__device__ int   g_csr_src[EDGE_MAX];
__device__ float g_ur1[256 * 4];
__device__ float g_ur2[256 * 4];
__device__ __nv_bfloat16 g_Ahi[NODES_MAX * 256];
__device__ __nv_bfloat16 g_Alo[NODES_MAX * 256];
__device__ __nv_bfloat16 g_B1hi[256 * 256];    // W1_src^T [n][k]
__device__ __nv_bfloat16 g_B1lo[256 * 256];
__device__ __nv_bfloat16 g_BChi[256 * 256];    // rows 0-127: W2^T, 128-255: Wres2^T
__device__ __nv_bfloat16 g_BClo[256 * 256];

// ---------------- low-level helpers ----------------
__device__ __forceinline__ uint32_t smem_u32(const void* p) {
    uint32_t a;
    asm("{ .reg .u64 t; cvta.to.shared.u64 t, %1; cvt.u32.u64 %0, t; }" : "=r"(a) : "l"(p));
    return a;
}
__device__ __forceinline__ uint32_t swz(uint32_t o) { return o ^ ((o >> 3) & 0x70); }
__device__ __forceinline__ void cp16(uint32_t dst, const void* src, int sz) {
    asm volatile("cp.async.cg.shared.global [%0], [%1], 16, %2;"
                 :: "r"(dst), "l"(src), "r"(sz) : "memory");
}
__device__ __forceinline__ void cp_commit() {
    asm volatile("cp.async.commit_group;" ::: "memory");
}
template <int N>
__device__ __forceinline__ void cp_wait() {
    asm volatile("cp.async.wait_group %0;" :: "n"(N) : "memory");
}
__device__ __forceinline__ void ldm4(uint32_t* r, uint32_t addr) {
    asm volatile("ldmatrix.sync.aligned.m8n8.x4.shared.b16 {%0,%1,%2,%3}, [%4];"
                 : "=r"(r[0]), "=r"(r[1]), "=r"(r[2]), "=r"(r[3]) : "r"(addr));
}
__device__ __forceinline__ void mma_bf16(float* d, const uint32_t* a, const uint32_t* b) {
    asm volatile(
        "mma.sync.aligned.m16n8k16.row.col.f32.bf16.bf16.f32 "
        "{%0,%1,%2,%3}, {%4,%5,%6,%7}, {%8,%9}, {%0,%1,%2,%3};"
        : "+f"(d[0]), "+f"(d[1]), "+f"(d[2]), "+f"(d[3])
        : "r"(a[0]), "r"(a[1]), "r"(a[2]), "r"(a[3]), "r"(b[0]), "r"(b[1]));
}
__device__ __forceinline__ float lrelu(float x) { return x < 0.f ? 0.2f * x : x; }

// ---------------- CSR build ----------------
__global__ void k_clear(int* cnt, int* cursor, float* el1, float* el2, int n) {
    int i = blockIdx.x * blockDim.x + threadIdx.x;
    if (i < n) { cnt[i] = 0; cursor[i] = 0; }
    if (i < 4 * n) { el1[i] = 0.f; el2[i] = 0.f; }
}
__global__ void k_count(const int* __restrict__ dst, int* cnt, int e_cnt) {
    int e = blockIdx.x * blockDim.x + threadIdx.x;
    if (e < e_cnt) atomicAdd(&cnt[dst[e]], 1);
}
__global__ void k_scan1(const int* __restrict__ cnt, int* rowptr, int* partial, int n) {
    __shared__ int sh[1024];
    int t = threadIdx.x;
    int idx = blockIdx.x * 1024 + t;
    int x = (idx < n) ? cnt[idx] : 0;
    sh[t] = x;
    __syncthreads();
    #pragma unroll
    for (int off = 1; off < 1024; off <<= 1) {
        int v = (t >= off) ? sh[t - off] : 0;
        __syncthreads();
        sh[t] += v;
        __syncthreads();
    }
    if (idx < n) rowptr[idx] = sh[t] - x;
    if (t == 1023) partial[blockIdx.x] = sh[1023];
}
// adds tile-prefix of partials (computed inline) to rowptr; block = 256 threads
__global__ void k_scan3(int* rowptr, const int* __restrict__ partial, int n, int e_cnt) {
    __shared__ int ws[2];
    __shared__ int s_off;
    int tid = threadIdx.x;
    int t4 = blockIdx.x >> 2;      // 1024-tile index of this 256-block
    if (tid < 64) {
        int v = (tid < t4) ? partial[tid] : 0;
        #pragma unroll
        for (int o = 16; o; o >>= 1) v += __shfl_xor_sync(0xFFFFFFFFu, v, o);
        if ((tid & 31) == 0) ws[tid >> 5] = v;
    }
    __syncthreads();
    if (tid == 0) s_off = ws[0] + ws[1];
    __syncthreads();
    int i = blockIdx.x * 256 + tid;
    if (i < n) rowptr[i] += s_off;
    if (blockIdx.x == 0 && tid == 0) rowptr[n] = e_cnt;
}
__global__ void k_fill(const int* __restrict__ src, const int* __restrict__ dst,
                       const int* __restrict__ rowptr, int* cursor, int* csr_src, int e_cnt) {
    int e = blockIdx.x * blockDim.x + threadIdx.x;
    if (e >= e_cnt) return;
    int d = dst[e];
    int p = rowptr[d] + atomicAdd(&cursor[d], 1);
    csr_src[p] = src[e];
}

// ---------------- weight prep: transpose+split B, ur vectors ----------------
__global__ void k_prep(const float* __restrict__ W1, const float* __restrict__ W2,
                       const float* __restrict__ W3,
                       const float* __restrict__ W1d, const float* __restrict__ ar1,
                       const float* __restrict__ W2d, const float* __restrict__ ar2,
                       __nv_bfloat16* b1h, __nv_bfloat16* b1l,
                       __nv_bfloat16* bch, __nv_bfloat16* bcl,
                       float* ur1, float* ur2) {
    int k = blockIdx.x;      // 0..255
    int n = threadIdx.x;
    if (blockIdx.y == 0) {
        float x = W1[k * 256 + n];
        __nv_bfloat16 h = __float2bfloat16(x);
        b1h[n * 256 + k] = h;
        b1l[n * 256 + k] = __float2bfloat16(x - __bfloat162float(h));
    } else if (blockIdx.y == 1) {
        if (n < 128) {
            float x = W2[k * 128 + n];
            __nv_bfloat16 h = __float2bfloat16(x);
            bch[n * 256 + k] = h;
            bcl[n * 256 + k] = __float2bfloat16(x - __bfloat162float(h));
        }
    } else if (blockIdx.y == 2) {
        if (n < 128) {
            float x = W3[k * 128 + n];
            __nv_bfloat16 h = __float2bfloat16(x);
            bch[(128 + n) * 256 + k] = h;
            bcl[(128 + n) * 256 + k] = __float2bfloat16(x - __bfloat162float(h));
        }
    } else if (blockIdx.x == 0) {
        for (int h = 0; h < 4; h++) {
            float s = 0.f;
            for (int d = 0; d < 64; d++) s += W1d[n * 256 + h * 64 + d] * ar1[h * 64 + d];
            ur1[n * 4 + h] = s;
        }
        for (int h = 0; h < 4; h++) {
            float s = 0.f;
            for (int d = 0; d < 32; d++) s += W2d[n * 128 + h * 32 + d] * ar2[h * 32 + d];
            ur2[n * 4 + h] = s;
        }
    }
}

// ---------------- convA + er (layer 1): warp per row ----------------
__global__ void k_convA_er(const float* __restrict__ A, __nv_bfloat16* __restrict__ hi,
                           __nv_bfloat16* __restrict__ lo, const float* __restrict__ ur,
                           float* __restrict__ er, int N) {
    int wid = threadIdx.x >> 5, lane = threadIdx.x & 31;
    int n = blockIdx.x * 8 + wid;
    if (n >= N) return;
    const float4* arow = (const float4*)&A[(size_t)n * 256];
    float4 v0 = arow[lane * 2];
    float4 v1 = arow[lane * 2 + 1];
    float vv[8] = {v0.x, v0.y, v0.z, v0.w, v1.x, v1.y, v1.z, v1.w};
    __nv_bfloat162 hp[4], lp[4];
    #pragma unroll
    for (int j = 0; j < 4; j++) {
        __nv_bfloat16 h0 = __float2bfloat16(vv[j * 2]);
        __nv_bfloat16 h1 = __float2bfloat16(vv[j * 2 + 1]);
        hp[j] = __nv_bfloat162(h0, h1);
        lp[j] = __nv_bfloat162(__float2bfloat16(vv[j * 2] - __bfloat162float(h0)),
                               __float2bfloat16(vv[j * 2 + 1] - __bfloat162float(h1)));
    }
    *(uint4*)&hi[(size_t)n * 256 + lane * 8] = *(uint4*)hp;
    *(uint4*)&lo[(size_t)n * 256 + lane * 8] = *(uint4*)lp;
    float4 e = make_float4(0.f, 0.f, 0.f, 0.f);
    const float4* ur4 = (const float4*)ur;
    int k = lane * 8;
    #pragma unroll
    for (int j = 0; j < 8; j++) {
        float4 u = ur4[k + j];
        e.x += vv[j] * u.x; e.y += vv[j] * u.y; e.z += vv[j] * u.z; e.w += vv[j] * u.w;
    }
    #pragma unroll
    for (int o = 16; o; o >>= 1) {
        e.x += __shfl_xor_sync(0xFFFFFFFFu, e.x, o);
        e.y += __shfl_xor_sync(0xFFFFFFFFu, e.y, o);
        e.z += __shfl_xor_sync(0xFFFFFFFFu, e.z, o);
        e.w += __shfl_xor_sync(0xFFFFFFFFu, e.w, o);
    }
    if (lane == 0) *(float4*)&er[n * 4] = e;
}

// ---------------- HMMA GEMM: tile 128x128, 512 thr, BK=64, double-buffered ----
// Output stride fixed 256. Computes el[r,h] += sum_d C[r, col]*al[col] in epilogue.
#define STG 65536
#define GEMM_SMEM (2 * STG)

__device__ __forceinline__ void ld_stage(uint32_t sb,
    const __nv_bfloat16* Ahi, const __nv_bfloat16* Alo,
    const __nv_bfloat16* Bhi, const __nv_bfloat16* Blo,
    int bm, int bn, int kb, int M, int t) {
    #pragma unroll
    for (int i = 0; i < 2; i++) {
        int id = t + i * 512;
        int r = id >> 3, c = id & 7;
        uint32_t o = swz((uint32_t)(r * 128 + c * 16));
        int ga = bm + r;
        int sz = (ga < M) ? 16 : 0;
        if (ga >= M) ga = M - 1;
        size_t so = (size_t)ga * 256 + kb * 64 + c * 8;
        cp16(sb + o, Ahi + so, sz);
        cp16(sb + 16384 + o, Alo + so, sz);
        size_t sob = (size_t)(bn + r) * 256 + kb * 64 + c * 8;
        cp16(sb + 32768 + o, Bhi + sob, 16);
        cp16(sb + 49152 + o, Blo + sob, 16);
    }
}

__global__ __launch_bounds__(512, 1) void k_mma(
    const __nv_bfloat16* __restrict__ Ahi, const __nv_bfloat16* __restrict__ Alo,
    const __nv_bfloat16* __restrict__ Bhi, const __nv_bfloat16* __restrict__ Blo,
    float* __restrict__ C, int M,
    float* __restrict__ el, const float* __restrict__ al, int hshift, int el_cols) {
    extern __shared__ char smem[];
    uint32_t sb = smem_u32(smem);
    int t = threadIdx.x;
    int lane = t & 31, wid = t >> 5;
    int wm = wid & 3, wn = wid >> 2;
    int bm = blockIdx.x * 128;
    int bn = blockIdx.y * 128;

    float acc[2][4][4];
    #pragma unroll
    for (int mt = 0; mt < 2; mt++)
        #pragma unroll
        for (int nt = 0; nt < 4; nt++)
            #pragma unroll
            for (int i = 0; i < 4; i++) acc[mt][nt][i] = 0.f;

    int a_row = wm * 32 + (lane & 15);
    int a_ch  = lane >> 4;
    int b_row = wn * 32 + (lane & 7) + ((lane >> 4) & 1) * 8;
    int b_ch  = (lane >> 3) & 1;

    ld_stage(sb, Ahi, Alo, Bhi, Blo, bm, bn, 0, M, t);
    cp_commit();

    #pragma unroll
    for (int kb = 0; kb < 4; kb++) {
        uint32_t stage = sb + (kb & 1) * STG;
        if (kb < 3) {
            ld_stage(sb + ((kb + 1) & 1) * STG, Ahi, Alo, Bhi, Blo, bm, bn, kb + 1, M, t);
            cp_commit();
            cp_wait<1>();
        } else {
            cp_wait<0>();
        }
        __syncthreads();

        #pragma unroll
        for (int ks = 0; ks < 4; ks++) {
            uint32_t ah[2][4], alr[2][4], bh[4][2], bl[4][2];
            #pragma unroll
            for (int mt = 0; mt < 2; mt++) {
                uint32_t off = swz((uint32_t)((a_row + mt * 16) * 128 + (ks * 2 + a_ch) * 16));
                ldm4(ah[mt], stage + off);
                ldm4(alr[mt], stage + 16384 + off);
            }
            #pragma unroll
            for (int p = 0; p < 2; p++) {
                uint32_t off = swz((uint32_t)((b_row + p * 16) * 128 + (ks * 2 + b_ch) * 16));
                uint32_t rh[4], rl[4];
                ldm4(rh, stage + 32768 + off);
                ldm4(rl, stage + 49152 + off);
                bh[p * 2][0] = rh[0]; bh[p * 2][1] = rh[1];
                bh[p * 2 + 1][0] = rh[2]; bh[p * 2 + 1][1] = rh[3];
                bl[p * 2][0] = rl[0]; bl[p * 2][1] = rl[1];
                bl[p * 2 + 1][0] = rl[2]; bl[p * 2 + 1][1] = rl[3];
            }
            #pragma unroll
            for (int mt = 0; mt < 2; mt++)
                #pragma unroll
                for (int nt = 0; nt < 4; nt++) {
                    mma_bf16(acc[mt][nt], ah[mt], bh[nt]);
                    mma_bf16(acc[mt][nt], alr[mt], bh[nt]);
                    mma_bf16(acc[mt][nt], ah[mt], bl[nt]);
                }
        }
        __syncthreads();
    }

    // C store
    #pragma unroll
    for (int mt = 0; mt < 2; mt++) {
        int r0 = bm + wm * 32 + mt * 16 + (lane >> 2);
        #pragma unroll
        for (int nt = 0; nt < 4; nt++) {
            int c0 = bn + wn * 32 + nt * 8 + (lane & 3) * 2;
            if (r0 < M)
                *(float2*)&C[(size_t)r0 * 256 + c0] = make_float2(acc[mt][nt][0], acc[mt][nt][1]);
            if (r0 + 8 < M)
                *(float2*)&C[(size_t)(r0 + 8) * 256 + c0] = make_float2(acc[mt][nt][2], acc[mt][nt][3]);
        }
    }

    // el epilogue: warp's 32 columns all belong to one head; al index == global col
    int colbase = bn + wn * 32;
    if (colbase < el_cols) {
        int h = colbase >> hshift;
        #pragma unroll
        for (int mt = 0; mt < 2; mt++) {
            float p0 = 0.f, p1 = 0.f;
            #pragma unroll
            for (int nt = 0; nt < 4; nt++) {
                int gc = colbase + nt * 8 + (lane & 3) * 2;
                float a0 = al[gc], a1 = al[gc + 1];
                p0 += acc[mt][nt][0] * a0 + acc[mt][nt][1] * a1;
                p1 += acc[mt][nt][2] * a0 + acc[mt][nt][3] * a1;
            }
            p0 += __shfl_xor_sync(0xFFFFFFFFu, p0, 1);
            p0 += __shfl_xor_sync(0xFFFFFFFFu, p0, 2);
            p1 += __shfl_xor_sync(0xFFFFFFFFu, p1, 1);
            p1 += __shfl_xor_sync(0xFFFFFFFFu, p1, 2);
            if ((lane & 3) == 0) {
                int r0 = bm + wm * 32 + mt * 16 + (lane >> 2);
                if (r0 < M) atomicAdd(&el[r0 * 4 + h], p0);
                if (r0 + 8 < M) atomicAdd(&el[(r0 + 8) * 4 + h], p1);
            }
        }
    }
}

// ---------------- single-pass register-cached segment softmax ----------------
__global__ void k_softmax(const int* __restrict__ rowptr, const int* __restrict__ csr_src,
                          const float* __restrict__ el, const float* __restrict__ er,
                          float* __restrict__ ex, int n_cnt) {
    int warp = (blockIdx.x * blockDim.x + threadIdx.x) >> 5;
    int lane = threadIdx.x & 31;
    if (warp >= n_cnt) return;
    int beg = rowptr[warp], end = rowptr[warp + 1];
    float4 erv = *(const float4*)&er[warp * 4];
    int deg = end - beg;
    if (deg <= 128) {
        float4 ec[4];
        float m0 = -1e30f, m1 = -1e30f, m2 = -1e30f, m3 = -1e30f;
        #pragma unroll
        for (int it = 0; it < 4; it++) {
            int j = beg + lane + it * 32;
            if (j < end) {
                int s = csr_src[j];
                float4 e = *(const float4*)&el[s * 4];
                e.x = lrelu(e.x + erv.x); e.y = lrelu(e.y + erv.y);
                e.z = lrelu(e.z + erv.z); e.w = lrelu(e.w + erv.w);
                ec[it] = e;
                m0 = fmaxf(m0, e.x); m1 = fmaxf(m1, e.y);
                m2 = fmaxf(m2, e.z); m3 = fmaxf(m3, e.w);
            }
        }
        #pragma unroll
        for (int o = 16; o; o >>= 1) {
            m0 = fmaxf(m0, __shfl_xor_sync(0xFFFFFFFFu, m0, o));
            m1 = fmaxf(m1, __shfl_xor_sync(0xFFFFFFFFu, m1, o));
            m2 = fmaxf(m2, __shfl_xor_sync(0xFFFFFFFFu, m2, o));
            m3 = fmaxf(m3, __shfl_xor_sync(0xFFFFFFFFu, m3, o));
        }
        float s0 = 0.f, s1 = 0.f, s2 = 0.f, s3 = 0.f;
        #pragma unroll
        for (int it = 0; it < 4; it++) {
            int j = beg + lane + it * 32;
            if (j < end) {
                ec[it].x = __expf(ec[it].x - m0); ec[it].y = __expf(ec[it].y - m1);
                ec[it].z = __expf(ec[it].z - m2); ec[it].w = __expf(ec[it].w - m3);
                s0 += ec[it].x; s1 += ec[it].y; s2 += ec[it].z; s3 += ec[it].w;
            }
        }
        #pragma unroll
        for (int o = 16; o; o >>= 1) {
            s0 += __shfl_xor_sync(0xFFFFFFFFu, s0, o);
            s1 += __shfl_xor_sync(0xFFFFFFFFu, s1, o);
            s2 += __shfl_xor_sync(0xFFFFFFFFu, s2, o);
            s3 += __shfl_xor_sync(0xFFFFFFFFu, s3, o);
        }
        float i0 = 1.f / s0, i1 = 1.f / s1, i2 = 1.f / s2, i3 = 1.f / s3;
        #pragma unroll
        for (int it = 0; it < 4; it++) {
            int j = beg + lane + it * 32;
            if (j < end) {
                ec[it].x *= i0; ec[it].y *= i1; ec[it].z *= i2; ec[it].w *= i3;
                *(float4*)&ex[(size_t)j * 4] = ec[it];
            }
        }
    } else {
        // fallback 3-pass (rare)
        float m0 = -1e30f, m1 = -1e30f, m2 = -1e30f, m3 = -1e30f;
        for (int j = beg + lane; j < end; j += 32) {
            int s = csr_src[j];
            float4 e = *(const float4*)&el[s * 4];
            e.x = lrelu(e.x + erv.x); e.y = lrelu(e.y + erv.y);
            e.z = lrelu(e.z + erv.z); e.w = lrelu(e.w + erv.w);
            *(float4*)&ex[(size_t)j * 4] = e;
            m0 = fmaxf(m0, e.x); m1 = fmaxf(m1, e.y); m2 = fmaxf(m2, e.z); m3 = fmaxf(m3, e.w);
        }
        #pragma unroll
        for (int o = 16; o; o >>= 1) {
            m0 = fmaxf(m0, __shfl_xor_sync(0xFFFFFFFFu, m0, o));
            m1 = fmaxf(m1, __shfl_xor_sync(0xFFFFFFFFu, m1, o));
            m2 = fmaxf(m2, __shfl_xor_sync(0xFFFFFFFFu, m2, o));
            m3 = fmaxf(m3, __shfl_xor_sync(0xFFFFFFFFu, m3, o));
        }
        float s0 = 0.f, s1 = 0.f, s2 = 0.f, s3 = 0.f;
        for (int j = beg + lane; j < end; j += 32) {
            float4 e = *(const float4*)&ex[(size_t)j * 4];
            e.x = __expf(e.x - m0); e.y = __expf(e.y - m1);
            e.z = __expf(e.z - m2); e.w = __expf(e.w - m3);
            *(float4*)&ex[(size_t)j * 4] = e;
            s0 += e.x; s1 += e.y; s2 += e.z; s3 += e.w;
        }
        #pragma unroll
        for (int o = 16; o; o >>= 1) {
            s0 += __shfl_xor_sync(0xFFFFFFFFu, s0, o);
            s1 += __shfl_xor_sync(0xFFFFFFFFu, s1, o);
            s2 += __shfl_xor_sync(0xFFFFFFFFu, s2, o);
            s3 += __shfl_xor_sync(0xFFFFFFFFu, s3, o);
        }
        float i0 = 1.f / s0, i1 = 1.f / s1, i2 = 1.f / s2, i3 = 1.f / s3;
        for (int j = beg + lane; j < end; j += 32) {
            float4 e = *(const float4*)&ex[(size_t)j * 4];
            e.x *= i0; e.y *= i1; e.z *= i2; e.w *= i3;
            *(float4*)&ex[(size_t)j * 4] = e;
        }
    }
}

// ---------------- agg layer 1: + residual + ELU + bf16 split + er2 ----------------
__global__ void k_agg1(const int* __restrict__ rowptr, const int* __restrict__ csr_src,
                       const float* __restrict__ ex, const float* __restrict__ fs,
                       const float* __restrict__ hin,
                       __nv_bfloat16* __restrict__ hi, __nv_bfloat16* __restrict__ lo,
                       const float* __restrict__ ur2, float* __restrict__ er2) {
    int n = blockIdx.x;
    int tid = threadIdx.x;          // 256
    int h = tid >> 6;
    int beg = rowptr[n], end = rowptr[n + 1];
    __shared__ int ss[64];
    __shared__ float4 wsum[8];
    float acc = 0.f;
    for (int base = beg; base < end; base += 64) {
        int m = min(64, end - base);
        __syncthreads();
        if (tid < m) ss[tid] = csr_src[base + tid];
        __syncthreads();
        #pragma unroll 4
        for (int i = 0; i < m; i++) {
            float w = ex[(size_t)(base + i) * 4 + h];
            acc += w * fs[(size_t)ss[i] * 256 + tid];
        }
    }
    float v = acc + hin[(size_t)n * 256 + tid];
    v = v > 0.f ? v : expm1f(v);
    __nv_bfloat16 vh = __float2bfloat16(v);
    hi[(size_t)n * 256 + tid] = vh;
    lo[(size_t)n * 256 + tid] = __float2bfloat16(v - __bfloat162float(vh));
    // er2 = h1_row . ur2
    float4 u = ((const float4*)ur2)[tid];
    float4 p = make_float4(v * u.x, v * u.y, v * u.z, v * u.w);
    #pragma unroll
    for (int o = 16; o; o >>= 1) {
        p.x += __shfl_xor_sync(0xFFFFFFFFu, p.x, o);
        p.y += __shfl_xor_sync(0xFFFFFFFFu, p.y, o);
        p.z += __shfl_xor_sync(0xFFFFFFFFu, p.z, o);
        p.w += __shfl_xor_sync(0xFFFFFFFFu, p.w, o);
    }
    if ((tid & 31) == 0) wsum[tid >> 5] = p;
    __syncthreads();
    if (tid == 0) {
        float4 s = wsum[0];
        #pragma unroll
        for (int i = 1; i < 8; i++) {
            s.x += wsum[i].x; s.y += wsum[i].y; s.z += wsum[i].z; s.w += wsum[i].w;
        }
        *(float4*)&er2[n * 4] = s;
    }
}

// ---------------- agg layer 2: + proj residual + head-mean ----------------
__global__ void k_agg2(const int* __restrict__ rowptr, const int* __restrict__ csr_src,
                       const float* __restrict__ ex, const float* __restrict__ c2,
                       float* __restrict__ out) {
    int n = blockIdx.x;
    int tid = threadIdx.x;          // 128
    int h = tid >> 5;
    int beg = rowptr[n], end = rowptr[n + 1];
    __shared__ int ss[64];
    __shared__ float sv[128];
    float acc = 0.f;
    for (int base = beg; base < end; base += 64) {
        int m = min(64, end - base);
        __syncthreads();
        if (tid < m) ss[tid] = csr_src[base + tid];
        __syncthreads();
        #pragma unroll 4
        for (int i = 0; i < m; i++) {
            float w = ex[(size_t)(base + i) * 4 + h];
            acc += w * c2[(size_t)ss[i] * 256 + tid];
        }
    }
    sv[tid] = acc + c2[(size_t)n * 256 + 128 + tid];
    __syncthreads();
    if (tid < 32)
        out[(size_t)n * 32 + tid] =
            (sv[tid] + sv[32 + tid] + sv[64 + tid] + sv[96 + tid]) * 0.25f;
}

// ---------------- launch ----------------
extern "C" void kernel_launch(void* const* d_in, const int* in_sizes, int n_in,
                              void* d_out, int out_size) {
    const float* h      = (const float*)d_in[0];
    const int*   src    = (const int*)d_in[1];
    const int*   dst    = (const int*)d_in[2];
    const float* W1_src = (const float*)d_in[3];
    const float* W1_dst = (const float*)d_in[4];
    const float* al1    = (const float*)d_in[5];
    const float* ar1    = (const float*)d_in[6];
    const float* W2_src = (const float*)d_in[7];
    const float* W2_dst = (const float*)d_in[8];
    const float* al2    = (const float*)d_in[9];
    const float* ar2    = (const float*)d_in[10];
    const float* Wres2  = (const float*)d_in[11];
    float* out = (float*)d_out;

    int N = in_sizes[0] / 256;
    int E = in_sizes[1];

    float *fs1, *c2, *el1, *el2, *er, *ex, *ur1, *ur2;
    int *cnt, *cursor, *rowptr, *partial, *csr_src;
    __nv_bfloat16 *Ahi, *Alo, *B1h, *B1l, *BCh, *BCl;
    cudaGetSymbolAddress((void**)&fs1, g_fs1);
    cudaGetSymbolAddress((void**)&c2, g_c2);
    cudaGetSymbolAddress((void**)&el1, g_el1);
    cudaGetSymbolAddress((void**)&el2, g_el2);
    cudaGetSymbolAddress((void**)&er, g_er);
    cudaGetSymbolAddress((void**)&ex, g_ex);
    cudaGetSymbolAddress((void**)&ur1, g_ur1);
    cudaGetSymbolAddress((void**)&ur2, g_ur2);
    cudaGetSymbolAddress((void**)&cnt, g_cnt);
    cudaGetSymbolAddress((void**)&cursor, g_cursor);
    cudaGetSymbolAddress((void**)&rowptr, g_rowptr);
    cudaGetSymbolAddress((void**)&partial, g_partial);
    cudaGetSymbolAddress((void**)&csr_src, g_csr_src);
    cudaGetSymbolAddress((void**)&Ahi, g_Ahi);
    cudaGetSymbolAddress((void**)&Alo, g_Alo);
    cudaGetSymbolAddress((void**)&B1h, g_B1hi);
    cudaGetSymbolAddress((void**)&B1l, g_B1lo);
    cudaGetSymbolAddress((void**)&BCh, g_BChi);
    cudaGetSymbolAddress((void**)&BCl, g_BClo);

    cudaFuncSetAttribute(k_mma, cudaFuncAttributeMaxDynamicSharedMemorySize, GEMM_SMEM);

    int gE = (E + 255) / 256;
    int gN4 = (N * 4 + 255) / 256;
    int gN = (N + 255) / 256;
    int nScanB = (N + 1023) / 1024;
    int gemmM = (N + 127) / 128;
    int gWarp = (N * 32 + 255) / 256;

    // CSR build + weight prep
    k_clear<<<gN4, 256>>>(cnt, cursor, el1, el2, N);
    k_count<<<gE, 256>>>(dst, cnt, E);
    k_scan1<<<nScanB, 1024>>>(cnt, rowptr, partial, N);
    k_scan3<<<gN, 256>>>(rowptr, partial, N, E);
    k_fill<<<gE, 256>>>(src, dst, rowptr, cursor, csr_src, E);
    k_prep<<<dim3(256, 4), 256>>>(W1_src, W2_src, Wres2, W1_dst, ar1, W2_dst, ar2,
                                  B1h, B1l, BCh, BCl, ur1, ur2);

    // ---- layer 1 ----
    k_convA_er<<<(N + 7) / 8, 256>>>(h, Ahi, Alo, ur1, er, N);
    k_mma<<<dim3(gemmM, 2), 512, GEMM_SMEM>>>(Ahi, Alo, B1h, B1l, fs1, N,
                                              el1, al1, 6, 256);
    k_softmax<<<gWarp, 256>>>(rowptr, csr_src, el1, er, ex, N);
    k_agg1<<<N, 256>>>(rowptr, csr_src, ex, fs1, h, Ahi, Alo, ur2, er);

    // ---- layer 2 ----
    k_mma<<<dim3(gemmM, 2), 512, GEMM_SMEM>>>(Ahi, Alo, BCh, BCl, c2, N,
                                              el2, al2, 5, 128);
    k_softmax<<<gWarp, 256>>>(rowptr, csr_src, el2, er, ex, N);
    k_agg2<<<N, 128>>>(rowptr, csr_src, ex, c2, out);
}

// round 5
// speedup vs baseline: 1.8288x; 1.1072x over previous
#include <cuda_runtime.h>
#include <cuda_bf16.h>
#include <cstdint>

// ---------------- problem capacities ----------------
#define NODES_MAX 50000
#define EDGE_MAX  860000

// ---------------- device scratch ----------------
__device__ float g_fs1[NODES_MAX * 256];
__device__ float g_c2 [NODES_MAX * 256];       // layer2 combined: cols 0-127 fs2, 128-255 res2
__device__ float g_el1[NODES_MAX * 4];
__device__ float g_el2[NODES_MAX * 4];
__device__ float g_er [NODES_MAX * 4];
__device__ int   g_cnt[NODES_MAX];
__device__ int   g_cursor[NODES_MAX];
__device__ int   g_rowptr[NODES_MAX + 1];
__device__ int   g_partial[64];
__device__ int   g_csr_src[EDGE_MAX];
__device__ float g_ur1[256 * 4];
__device__ float g_ur2[256 * 4];
__device__ __nv_bfloat16 g_Ahi[NODES_MAX * 256];
__device__ __nv_bfloat16 g_Alo[NODES_MAX * 256];
__device__ __nv_bfloat16 g_B1hi[256 * 256];    // W1_src^T [n][k]
__device__ __nv_bfloat16 g_B1lo[256 * 256];
__device__ __nv_bfloat16 g_BChi[256 * 256];    // rows 0-127: W2^T, 128-255: Wres2^T
__device__ __nv_bfloat16 g_BClo[256 * 256];

// ---------------- low-level helpers ----------------
__device__ __forceinline__ uint32_t smem_u32(const void* p) {
    uint32_t a;
    asm("{ .reg .u64 t; cvta.to.shared.u64 t, %1; cvt.u32.u64 %0, t; }" : "=r"(a) : "l"(p));
    return a;
}
__device__ __forceinline__ uint32_t swz(uint32_t o) { return o ^ ((o >> 3) & 0x70); }
__device__ __forceinline__ void cp16(uint32_t dst, const void* src, int sz) {
    asm volatile("cp.async.cg.shared.global [%0], [%1], 16, %2;"
                 :: "r"(dst), "l"(src), "r"(sz) : "memory");
}
__device__ __forceinline__ void cp_commit() {
    asm volatile("cp.async.commit_group;" ::: "memory");
}
template <int N>
__device__ __forceinline__ void cp_wait() {
    asm volatile("cp.async.wait_group %0;" :: "n"(N) : "memory");
}
__device__ __forceinline__ void ldm4(uint32_t* r, uint32_t addr) {
    asm volatile("ldmatrix.sync.aligned.m8n8.x4.shared.b16 {%0,%1,%2,%3}, [%4];"
                 : "=r"(r[0]), "=r"(r[1]), "=r"(r[2]), "=r"(r[3]) : "r"(addr));
}
__device__ __forceinline__ void mma_bf16(float* d, const uint32_t* a, const uint32_t* b) {
    asm volatile(
        "mma.sync.aligned.m16n8k16.row.col.f32.bf16.bf16.f32 "
        "{%0,%1,%2,%3}, {%4,%5,%6,%7}, {%8,%9}, {%0,%1,%2,%3};"
        : "+f"(d[0]), "+f"(d[1]), "+f"(d[2]), "+f"(d[3])
        : "r"(a[0]), "r"(a[1]), "r"(a[2]), "r"(a[3]), "r"(b[0]), "r"(b[1]));
}
__device__ __forceinline__ float lrelu(float x) { return x < 0.f ? 0.2f * x : x; }

// ---------------- CSR build ----------------
__global__ void k_clear(int* cnt, int* cursor, float* el1, float* el2, int n) {
    int i = blockIdx.x * blockDim.x + threadIdx.x;
    if (i < n) { cnt[i] = 0; cursor[i] = 0; }
    if (i < 4 * n) { el1[i] = 0.f; el2[i] = 0.f; }
}
__global__ void k_count(const int* __restrict__ dst, int* cnt, int e_cnt) {
    int e = blockIdx.x * blockDim.x + threadIdx.x;
    if (e < e_cnt) atomicAdd(&cnt[dst[e]], 1);
}
__global__ void k_scan1(const int* __restrict__ cnt, int* rowptr, int* partial, int n) {
    __shared__ int sh[1024];
    int t = threadIdx.x;
    int idx = blockIdx.x * 1024 + t;
    int x = (idx < n) ? cnt[idx] : 0;
    sh[t] = x;
    __syncthreads();
    #pragma unroll
    for (int off = 1; off < 1024; off <<= 1) {
        int v = (t >= off) ? sh[t - off] : 0;
        __syncthreads();
        sh[t] += v;
        __syncthreads();
    }
    if (idx < n) rowptr[idx] = sh[t] - x;
    if (t == 1023) partial[blockIdx.x] = sh[1023];
}
__global__ void k_scan3(int* rowptr, const int* __restrict__ partial, int n, int e_cnt) {
    __shared__ int ws[2];
    __shared__ int s_off;
    int tid = threadIdx.x;
    int t4 = blockIdx.x >> 2;
    if (tid < 64) {
        int v = (tid < t4) ? partial[tid] : 0;
        #pragma unroll
        for (int o = 16; o; o >>= 1) v += __shfl_xor_sync(0xFFFFFFFFu, v, o);
        if ((tid & 31) == 0) ws[tid >> 5] = v;
    }
    __syncthreads();
    if (tid == 0) s_off = ws[0] + ws[1];
    __syncthreads();
    int i = blockIdx.x * 256 + tid;
    if (i < n) rowptr[i] += s_off;
    if (blockIdx.x == 0 && tid == 0) rowptr[n] = e_cnt;
}
__global__ void k_fill(const int* __restrict__ src, const int* __restrict__ dst,
                       const int* __restrict__ rowptr, int* cursor, int* csr_src, int e_cnt) {
    int e = blockIdx.x * blockDim.x + threadIdx.x;
    if (e >= e_cnt) return;
    int d = dst[e];
    int p = rowptr[d] + atomicAdd(&cursor[d], 1);
    csr_src[p] = src[e];
}

// ---------------- weight prep ----------------
__global__ void k_prep(const float* __restrict__ W1, const float* __restrict__ W2,
                       const float* __restrict__ W3,
                       const float* __restrict__ W1d, const float* __restrict__ ar1,
                       const float* __restrict__ W2d, const float* __restrict__ ar2,
                       __nv_bfloat16* b1h, __nv_bfloat16* b1l,
                       __nv_bfloat16* bch, __nv_bfloat16* bcl,
                       float* ur1, float* ur2) {
    int k = blockIdx.x;
    int n = threadIdx.x;
    if (blockIdx.y == 0) {
        float x = W1[k * 256 + n];
        __nv_bfloat16 h = __float2bfloat16(x);
        b1h[n * 256 + k] = h;
        b1l[n * 256 + k] = __float2bfloat16(x - __bfloat162float(h));
    } else if (blockIdx.y == 1) {
        if (n < 128) {
            float x = W2[k * 128 + n];
            __nv_bfloat16 h = __float2bfloat16(x);
            bch[n * 256 + k] = h;
            bcl[n * 256 + k] = __float2bfloat16(x - __bfloat162float(h));
        }
    } else if (blockIdx.y == 2) {
        if (n < 128) {
            float x = W3[k * 128 + n];
            __nv_bfloat16 h = __float2bfloat16(x);
            bch[(128 + n) * 256 + k] = h;
            bcl[(128 + n) * 256 + k] = __float2bfloat16(x - __bfloat162float(h));
        }
    } else if (blockIdx.x == 0) {
        for (int h = 0; h < 4; h++) {
            float s = 0.f;
            for (int d = 0; d < 64; d++) s += W1d[n * 256 + h * 64 + d] * ar1[h * 64 + d];
            ur1[n * 4 + h] = s;
        }
        for (int h = 0; h < 4; h++) {
            float s = 0.f;
            for (int d = 0; d < 32; d++) s += W2d[n * 128 + h * 32 + d] * ar2[h * 32 + d];
            ur2[n * 4 + h] = s;
        }
    }
}

// ---------------- convA + er (layer 1) ----------------
__global__ void k_convA_er(const float* __restrict__ A, __nv_bfloat16* __restrict__ hi,
                           __nv_bfloat16* __restrict__ lo, const float* __restrict__ ur,
                           float* __restrict__ er, int N) {
    int wid = threadIdx.x >> 5, lane = threadIdx.x & 31;
    int n = blockIdx.x * 8 + wid;
    if (n >= N) return;
    const float4* arow = (const float4*)&A[(size_t)n * 256];
    float4 v0 = arow[lane * 2];
    float4 v1 = arow[lane * 2 + 1];
    float vv[8] = {v0.x, v0.y, v0.z, v0.w, v1.x, v1.y, v1.z, v1.w};
    __nv_bfloat162 hp[4], lp[4];
    #pragma unroll
    for (int j = 0; j < 4; j++) {
        __nv_bfloat16 h0 = __float2bfloat16(vv[j * 2]);
        __nv_bfloat16 h1 = __float2bfloat16(vv[j * 2 + 1]);
        hp[j] = __nv_bfloat162(h0, h1);
        lp[j] = __nv_bfloat162(__float2bfloat16(vv[j * 2] - __bfloat162float(h0)),
                               __float2bfloat16(vv[j * 2 + 1] - __bfloat162float(h1)));
    }
    *(uint4*)&hi[(size_t)n * 256 + lane * 8] = *(uint4*)hp;
    *(uint4*)&lo[(size_t)n * 256 + lane * 8] = *(uint4*)lp;
    float4 e = make_float4(0.f, 0.f, 0.f, 0.f);
    const float4* ur4 = (const float4*)ur;
    int k = lane * 8;
    #pragma unroll
    for (int j = 0; j < 8; j++) {
        float4 u = ur4[k + j];
        e.x += vv[j] * u.x; e.y += vv[j] * u.y; e.z += vv[j] * u.z; e.w += vv[j] * u.w;
    }
    #pragma unroll
    for (int o = 16; o; o >>= 1) {
        e.x += __shfl_xor_sync(0xFFFFFFFFu, e.x, o);
        e.y += __shfl_xor_sync(0xFFFFFFFFu, e.y, o);
        e.z += __shfl_xor_sync(0xFFFFFFFFu, e.z, o);
        e.w += __shfl_xor_sync(0xFFFFFFFFu, e.w, o);
    }
    if (lane == 0) *(float4*)&er[n * 4] = e;
}

// ---------------- HMMA GEMM: tile 128x128, 512 thr, BK=64, double-buffered ----
#define STG 65536
#define GEMM_SMEM (2 * STG)

__device__ __forceinline__ void ld_stage(uint32_t sb,
    const __nv_bfloat16* Ahi, const __nv_bfloat16* Alo,
    const __nv_bfloat16* Bhi, const __nv_bfloat16* Blo,
    int bm, int bn, int kb, int M, int t) {
    #pragma unroll
    for (int i = 0; i < 2; i++) {
        int id = t + i * 512;
        int r = id >> 3, c = id & 7;
        uint32_t o = swz((uint32_t)(r * 128 + c * 16));
        int ga = bm + r;
        int sz = (ga < M) ? 16 : 0;
        if (ga >= M) ga = M - 1;
        size_t so = (size_t)ga * 256 + kb * 64 + c * 8;
        cp16(sb + o, Ahi + so, sz);
        cp16(sb + 16384 + o, Alo + so, sz);
        size_t sob = (size_t)(bn + r) * 256 + kb * 64 + c * 8;
        cp16(sb + 32768 + o, Bhi + sob, 16);
        cp16(sb + 49152 + o, Blo + sob, 16);
    }
}

__global__ __launch_bounds__(512, 1) void k_mma(
    const __nv_bfloat16* __restrict__ Ahi, const __nv_bfloat16* __restrict__ Alo,
    const __nv_bfloat16* __restrict__ Bhi, const __nv_bfloat16* __restrict__ Blo,
    float* __restrict__ C, int M,
    float* __restrict__ el, const float* __restrict__ al, int hshift, int el_cols) {
    extern __shared__ char smem[];
    uint32_t sb = smem_u32(smem);
    int t = threadIdx.x;
    int lane = t & 31, wid = t >> 5;
    int wm = wid & 3, wn = wid >> 2;
    int bm = blockIdx.x * 128;
    int bn = blockIdx.y * 128;

    float acc[2][4][4];
    #pragma unroll
    for (int mt = 0; mt < 2; mt++)
        #pragma unroll
        for (int nt = 0; nt < 4; nt++)
            #pragma unroll
            for (int i = 0; i < 4; i++) acc[mt][nt][i] = 0.f;

    int a_row = wm * 32 + (lane & 15);
    int a_ch  = lane >> 4;
    int b_row = wn * 32 + (lane & 7) + ((lane >> 4) & 1) * 8;
    int b_ch  = (lane >> 3) & 1;

    ld_stage(sb, Ahi, Alo, Bhi, Blo, bm, bn, 0, M, t);
    cp_commit();

    #pragma unroll
    for (int kb = 0; kb < 4; kb++) {
        uint32_t stage = sb + (kb & 1) * STG;
        if (kb < 3) {
            ld_stage(sb + ((kb + 1) & 1) * STG, Ahi, Alo, Bhi, Blo, bm, bn, kb + 1, M, t);
            cp_commit();
            cp_wait<1>();
        } else {
            cp_wait<0>();
        }
        __syncthreads();

        #pragma unroll
        for (int ks = 0; ks < 4; ks++) {
            uint32_t ah[2][4], alr[2][4], bh[4][2], bl[4][2];
            #pragma unroll
            for (int mt = 0; mt < 2; mt++) {
                uint32_t off = swz((uint32_t)((a_row + mt * 16) * 128 + (ks * 2 + a_ch) * 16));
                ldm4(ah[mt], stage + off);
                ldm4(alr[mt], stage + 16384 + off);
            }
            #pragma unroll
            for (int p = 0; p < 2; p++) {
                uint32_t off = swz((uint32_t)((b_row + p * 16) * 128 + (ks * 2 + b_ch) * 16));
                uint32_t rh[4], rl[4];
                ldm4(rh, stage + 32768 + off);
                ldm4(rl, stage + 49152 + off);
                bh[p * 2][0] = rh[0]; bh[p * 2][1] = rh[1];
                bh[p * 2 + 1][0] = rh[2]; bh[p * 2 + 1][1] = rh[3];
                bl[p * 2][0] = rl[0]; bl[p * 2][1] = rl[1];
                bl[p * 2 + 1][0] = rl[2]; bl[p * 2 + 1][1] = rl[3];
            }
            #pragma unroll
            for (int mt = 0; mt < 2; mt++)
                #pragma unroll
                for (int nt = 0; nt < 4; nt++) {
                    mma_bf16(acc[mt][nt], ah[mt], bh[nt]);
                    mma_bf16(acc[mt][nt], alr[mt], bh[nt]);
                    mma_bf16(acc[mt][nt], ah[mt], bl[nt]);
                }
        }
        __syncthreads();
    }

    #pragma unroll
    for (int mt = 0; mt < 2; mt++) {
        int r0 = bm + wm * 32 + mt * 16 + (lane >> 2);
        #pragma unroll
        for (int nt = 0; nt < 4; nt++) {
            int c0 = bn + wn * 32 + nt * 8 + (lane & 3) * 2;
            if (r0 < M)
                *(float2*)&C[(size_t)r0 * 256 + c0] = make_float2(acc[mt][nt][0], acc[mt][nt][1]);
            if (r0 + 8 < M)
                *(float2*)&C[(size_t)(r0 + 8) * 256 + c0] = make_float2(acc[mt][nt][2], acc[mt][nt][3]);
        }
    }

    int colbase = bn + wn * 32;
    if (colbase < el_cols) {
        int h = colbase >> hshift;
        #pragma unroll
        for (int mt = 0; mt < 2; mt++) {
            float p0 = 0.f, p1 = 0.f;
            #pragma unroll
            for (int nt = 0; nt < 4; nt++) {
                int gc = colbase + nt * 8 + (lane & 3) * 2;
                float a0 = al[gc], a1 = al[gc + 1];
                p0 += acc[mt][nt][0] * a0 + acc[mt][nt][1] * a1;
                p1 += acc[mt][nt][2] * a0 + acc[mt][nt][3] * a1;
            }
            p0 += __shfl_xor_sync(0xFFFFFFFFu, p0, 1);
            p0 += __shfl_xor_sync(0xFFFFFFFFu, p0, 2);
            p1 += __shfl_xor_sync(0xFFFFFFFFu, p1, 1);
            p1 += __shfl_xor_sync(0xFFFFFFFFu, p1, 2);
            if ((lane & 3) == 0) {
                int r0 = bm + wm * 32 + mt * 16 + (lane >> 2);
                if (r0 < M) atomicAdd(&el[r0 * 4 + h], p0);
                if (r0 + 8 < M) atomicAdd(&el[(r0 + 8) * 4 + h], p1);
            }
        }
    }
}

// ---------------- agg layer 1 (fused softmax, no-max): + residual + ELU + bf16 + er2 ----
__global__ void k_agg1(const int* __restrict__ rowptr, const int* __restrict__ csr_src,
                       const float* __restrict__ el, const float* __restrict__ er,
                       const float* __restrict__ fs, const float* __restrict__ hin,
                       __nv_bfloat16* __restrict__ hi, __nv_bfloat16* __restrict__ lo,
                       const float* __restrict__ ur2, float* __restrict__ er2) {
    int n = blockIdx.x;
    int tid = threadIdx.x;          // 256
    int h = tid >> 6;
    int wi = tid & 63;
    int beg = rowptr[n], end = rowptr[n + 1];
    __shared__ int ss[64];
    __shared__ float sw[4][64];
    __shared__ float red[8];
    __shared__ float4 wsum[8];
    float erh = er[n * 4 + h];
    float acc = 0.f, denp = 0.f;
    for (int base = beg; base < end; base += 64) {
        int m = min(64, end - base);
        __syncthreads();
        if (tid < m) ss[tid] = csr_src[base + tid];
        __syncthreads();
        float w = 0.f;
        if (wi < m) {
            int s = ss[wi];
            w = __expf(lrelu(el[s * 4 + h] + erh));
        }
        sw[h][wi] = w;
        denp += w;
        __syncthreads();
        #pragma unroll 4
        for (int i = 0; i < m; i++)
            acc += sw[h][i] * fs[(size_t)ss[i] * 256 + tid];
    }
    #pragma unroll
    for (int o = 16; o; o >>= 1) denp += __shfl_xor_sync(0xFFFFFFFFu, denp, o);
    if ((tid & 31) == 0) red[tid >> 5] = denp;
    __syncthreads();
    float den = red[2 * h] + red[2 * h + 1];
    float v = acc / den + hin[(size_t)n * 256 + tid];
    v = v > 0.f ? v : expm1f(v);
    __nv_bfloat16 vh = __float2bfloat16(v);
    hi[(size_t)n * 256 + tid] = vh;
    lo[(size_t)n * 256 + tid] = __float2bfloat16(v - __bfloat162float(vh));
    float4 u = ((const float4*)ur2)[tid];
    float4 p = make_float4(v * u.x, v * u.y, v * u.z, v * u.w);
    #pragma unroll
    for (int o = 16; o; o >>= 1) {
        p.x += __shfl_xor_sync(0xFFFFFFFFu, p.x, o);
        p.y += __shfl_xor_sync(0xFFFFFFFFu, p.y, o);
        p.z += __shfl_xor_sync(0xFFFFFFFFu, p.z, o);
        p.w += __shfl_xor_sync(0xFFFFFFFFu, p.w, o);
    }
    if ((tid & 31) == 0) wsum[tid >> 5] = p;
    __syncthreads();
    if (tid == 0) {
        float4 s = wsum[0];
        #pragma unroll
        for (int i = 1; i < 8; i++) {
            s.x += wsum[i].x; s.y += wsum[i].y; s.z += wsum[i].z; s.w += wsum[i].w;
        }
        *(float4*)&er2[n * 4] = s;
    }
}

// ---------------- agg layer 2 (fused softmax, no-max): + proj residual + head-mean ----
__global__ void k_agg2(const int* __restrict__ rowptr, const int* __restrict__ csr_src,
                       const float* __restrict__ el, const float* __restrict__ er,
                       const float* __restrict__ c2, float* __restrict__ out) {
    int n = blockIdx.x;
    int tid = threadIdx.x;          // 128
    int h = tid >> 5;
    int wi = tid & 63;
    int whb = (tid >> 6) * 2;       // weight-duty heads {whb, whb+1}
    int beg = rowptr[n], end = rowptr[n + 1];
    __shared__ int ss[64];
    __shared__ float sw[4][64];
    __shared__ float red[4][2];
    __shared__ float sv[128];
    float er0 = er[n * 4 + whb], er1 = er[n * 4 + whb + 1];
    float acc = 0.f, den0 = 0.f, den1 = 0.f;
    for (int base = beg; base < end; base += 64) {
        int m = min(64, end - base);
        __syncthreads();
        if (tid < m) ss[tid] = csr_src[base + tid];
        if (tid + 128 < m) ss[tid + 128] = csr_src[base + tid + 128];  // unreachable (m<=64)
        __syncthreads();
        float w0 = 0.f, w1 = 0.f;
        if (wi < m) {
            int s = ss[wi];
            float2 ev = *(const float2*)&el[s * 4 + whb];
            w0 = __expf(lrelu(ev.x + er0));
            w1 = __expf(lrelu(ev.y + er1));
        }
        sw[whb][wi] = w0;
        sw[whb + 1][wi] = w1;
        den0 += w0; den1 += w1;
        __syncthreads();
        #pragma unroll 4
        for (int i = 0; i < m; i++)
            acc += sw[h][i] * c2[(size_t)ss[i] * 256 + tid];
    }
    #pragma unroll
    for (int o = 16; o; o >>= 1) {
        den0 += __shfl_xor_sync(0xFFFFFFFFu, den0, o);
        den1 += __shfl_xor_sync(0xFFFFFFFFu, den1, o);
    }
    if ((tid & 31) == 0) { red[tid >> 5][0] = den0; red[tid >> 5][1] = den1; }
    __syncthreads();
    float den = red[(h >> 1) * 2][h & 1] + red[(h >> 1) * 2 + 1][h & 1];
    sv[tid] = acc / den + c2[(size_t)n * 256 + 128 + tid];
    __syncthreads();
    if (tid < 32)
        out[(size_t)n * 32 + tid] =
            (sv[tid] + sv[32 + tid] + sv[64 + tid] + sv[96 + tid]) * 0.25f;
}

// ---------------- launch ----------------
extern "C" void kernel_launch(void* const* d_in, const int* in_sizes, int n_in,
                              void* d_out, int out_size) {
    const float* h      = (const float*)d_in[0];
    const int*   src    = (const int*)d_in[1];
    const int*   dst    = (const int*)d_in[2];
    const float* W1_src = (const float*)d_in[3];
    const float* W1_dst = (const float*)d_in[4];
    const float* al1    = (const float*)d_in[5];
    const float* ar1    = (const float*)d_in[6];
    const float* W2_src = (const float*)d_in[7];
    const float* W2_dst = (const float*)d_in[8];
    const float* al2    = (const float*)d_in[9];
    const float* ar2    = (const float*)d_in[10];
    const float* Wres2  = (const float*)d_in[11];
    float* out = (float*)d_out;

    int N = in_sizes[0] / 256;
    int E = in_sizes[1];

    float *fs1, *c2, *el1, *el2, *er, *ur1, *ur2;
    int *cnt, *cursor, *rowptr, *partial, *csr_src;
    __nv_bfloat16 *Ahi, *Alo, *B1h, *B1l, *BCh, *BCl;
    cudaGetSymbolAddress((void**)&fs1, g_fs1);
    cudaGetSymbolAddress((void**)&c2, g_c2);
    cudaGetSymbolAddress((void**)&el1, g_el1);
    cudaGetSymbolAddress((void**)&el2, g_el2);
    cudaGetSymbolAddress((void**)&er, g_er);
    cudaGetSymbolAddress((void**)&ur1, g_ur1);
    cudaGetSymbolAddress((void**)&ur2, g_ur2);
    cudaGetSymbolAddress((void**)&cnt, g_cnt);
    cudaGetSymbolAddress((void**)&cursor, g_cursor);
    cudaGetSymbolAddress((void**)&rowptr, g_rowptr);
    cudaGetSymbolAddress((void**)&partial, g_partial);
    cudaGetSymbolAddress((void**)&csr_src, g_csr_src);
    cudaGetSymbolAddress((void**)&Ahi, g_Ahi);
    cudaGetSymbolAddress((void**)&Alo, g_Alo);
    cudaGetSymbolAddress((void**)&B1h, g_B1hi);
    cudaGetSymbolAddress((void**)&B1l, g_B1lo);
    cudaGetSymbolAddress((void**)&BCh, g_BChi);
    cudaGetSymbolAddress((void**)&BCl, g_BClo);

    static cudaStream_t s1 = nullptr;
    static cudaEvent_t ev0 = nullptr, ev1 = nullptr;
    if (!s1) {
        cudaStreamCreateWithFlags(&s1, cudaStreamNonBlocking);
        cudaEventCreateWithFlags(&ev0, cudaEventDisableTiming);
        cudaEventCreateWithFlags(&ev1, cudaEventDisableTiming);
        cudaFuncSetAttribute(k_mma, cudaFuncAttributeMaxDynamicSharedMemorySize, GEMM_SMEM);
    }

    int gE = (E + 255) / 256;
    int gN4 = (N * 4 + 255) / 256;
    int gN = (N + 255) / 256;
    int nScanB = (N + 1023) / 1024;
    int gemmM = (N + 127) / 128;

    // clear on main stream (needed by both branches)
    k_clear<<<gN4, 256>>>(cnt, cursor, el1, el2, N);
    cudaEventRecord(ev0, 0);

    // ---- side stream: CSR build ----
    cudaStreamWaitEvent(s1, ev0, 0);
    k_count<<<gE, 256, 0, s1>>>(dst, cnt, E);
    k_scan1<<<nScanB, 1024, 0, s1>>>(cnt, rowptr, partial, N);
    k_scan3<<<gN, 256, 0, s1>>>(rowptr, partial, N, E);
    k_fill<<<gE, 256, 0, s1>>>(src, dst, rowptr, cursor, csr_src, E);
    cudaEventRecord(ev1, s1);

    // ---- main stream: weight prep + convert + GEMM L1 ----
    k_prep<<<dim3(256, 4), 256>>>(W1_src, W2_src, Wres2, W1_dst, ar1, W2_dst, ar2,
                                  B1h, B1l, BCh, BCl, ur1, ur2);
    k_convA_er<<<(N + 7) / 8, 256>>>(h, Ahi, Alo, ur1, er, N);
    k_mma<<<dim3(gemmM, 2), 512, GEMM_SMEM>>>(Ahi, Alo, B1h, B1l, fs1, N, el1, al1, 6, 256);

    // join CSR branch, then fused softmax+aggregation
    cudaStreamWaitEvent(0, ev1, 0);
    k_agg1<<<N, 256>>>(rowptr, csr_src, el1, er, fs1, h, Ahi, Alo, ur2, er);

    // ---- layer 2 ----
    k_mma<<<dim3(gemmM, 2), 512, GEMM_SMEM>>>(Ahi, Alo, BCh, BCl, c2, N, el2, al2, 5, 128);
    k_agg2<<<N, 128>>>(rowptr, csr_src, el2, er, c2, out);
}